// round 12
// baseline (speedup 1.0000x reference)
#include <cuda_runtime.h>
#include <cuda_bf16.h>
#include <math.h>
#include <stdint.h>
#include <string.h>

#define Bc 4
#define Nv 2466
#define BN (Bc * Nv)          // 9864
#define NBR_CAP 96
#define GM BN
#define KPAD 320              // 5 K-blocks of 64 (max K=259)
#define KF 3840               // aligned-feature K (sum of conv channels)

// ---------------- scratch (device globals; no allocs) ----------------
__device__ float g_hf[BN * 128];   // float h scratch
__device__ float g_skip[BN * 128];
__device__ float g_t[BN * 128];
__device__ float g_h2[BN * 128];
__device__ float g_h3[BN * 3];
__device__ float g_t3[BN * 3];
__device__ int   g_nbr[BN * NBR_CAP];
__device__ int   g_ncnt[BN];
__device__ int   g_act_off[4 * BN];
__device__ float g_act_wg[4 * BN];
__device__ float g_apart[BN * 128];   // align GEMM output per active slot
__device__ int   g_act_cnt;
__device__ int   g_slot[BN];
__device__ __nv_bfloat16 g_wt_hi[15 * 128 * KPAD];  // W^T [slab][n][k]
__device__ __nv_bfloat16 g_wt_lo[15 * 128 * KPAD];
__device__ __nv_bfloat16 g_lw_hi[128 * KF];         // lin_w^T [n][k]
__device__ __nv_bfloat16 g_lw_lo[128 * KF];
__device__ __nv_bfloat16 g_fhi[(size_t)BN * KF];    // gathered active features
__device__ __nv_bfloat16 g_flo[(size_t)BN * KF];
__device__ __nv_bfloat16 g_ahi[BN * KPAD];          // stage-0 X split (zero-padded)
__device__ __nv_bfloat16 g_alo[BN * KPAD];
__device__ __nv_bfloat16 g_hhi[BN * 128];           // mid-stage h split
__device__ __nv_bfloat16 g_hlo[BN * 128];
__device__ __nv_bfloat16 g_ohi[BN * 128];           // stage-output split
__device__ __nv_bfloat16 g_olo[BN * 128];

// ---------------- helpers ----------------
__device__ __forceinline__ uint32_t smem_u32(const void* p) {
    uint32_t a;
    asm("{ .reg .u64 t; cvta.to.shared.u64 t, %1; cvt.u32.u64 %0, t; }" : "=r"(a) : "l"(p));
    return a;
}

#define LDSM_X4(r0, r1, r2, r3, addr)                                            \
    asm volatile("ldmatrix.sync.aligned.m8n8.x4.shared.b16 {%0,%1,%2,%3}, [%4];" \
        : "=r"(r0), "=r"(r1), "=r"(r2), "=r"(r3) : "r"(addr))

#define CP_ASYNC16(dst, src, sz)                                                 \
    asm volatile("cp.async.cg.shared.global [%0], [%1], 16, %2;"                 \
        :: "r"(dst), "l"(src), "r"(sz))
#define CP_COMMIT() asm volatile("cp.async.commit_group;")
#define CP_WAIT0()  asm volatile("cp.async.wait_group 0;")

__device__ __forceinline__ void mma_bf16(float* d, const uint32_t* a,
                                         uint32_t b0, uint32_t b1) {
    asm volatile(
        "mma.sync.aligned.m16n8k16.row.col.f32.bf16.bf16.f32 "
        "{%0,%1,%2,%3}, {%4,%5,%6,%7}, {%8,%9}, {%0,%1,%2,%3};"
        : "+f"(d[0]), "+f"(d[1]), "+f"(d[2]), "+f"(d[3])
        : "r"(a[0]), "r"(a[1]), "r"(a[2]), "r"(a[3]), "r"(b0), "r"(b1));
}

// ---------------- vertex projection / active-list build ----------------
__global__ void k_prep(const float* __restrict__ pos) {
    int v = blockIdx.x * blockDim.x + threadIdx.x;
    if (v >= BN) return;
    g_slot[v] = -1;
    int b = v / Nv;
    float px = pos[v * 3 + 0], py = pos[v * 3 + 1], pz = pos[v * 3 + 2];
    float h = 248.f * (py / pz) + 111.5f;
    h = fminf(fmaxf(h, 0.f), 223.f);
    float w = 248.f * (px / (-pz)) + 111.5f;
    w = fminf(fmaxf(w, 0.f), 223.f);

    const int   Ss[4] = {56, 28, 14, 7};
    const int   Cs[4] = {256, 512, 1024, 2048};
    const float rs[4] = {0.25f, 0.125f, 0.0625f, 0.03125f};

    int off[4]; float wg[4]; bool any = false;
#pragma unroll
    for (int m = 0; m < 4; m++) {
        int S = Ss[m];
        float x = h * rs[m], y = w * rs[m];
        int x1 = (int)floorf(x);
        int x2 = min((int)ceilf(x), S - 1);
        int y1 = (int)floorf(y);
        int y2 = min((int)ceilf(y), S - 1);
        int wi = (x2 - x1) * (y2 - y1);
        off[m] = b * Cs[m] * S * S + x1 * S + y1;
        wg[m] = (float)wi;
        any = any || (wi != 0);
    }
    if (any) {
        int slot = atomicAdd(&g_act_cnt, 1);
        g_slot[v] = slot;
#pragma unroll
        for (int m = 0; m < 4; m++) {
            g_act_off[m * BN + slot] = off[m];
            g_act_wg[m * BN + slot]  = wg[m];
        }
    }
}

// ---------------- gather active-vertex weighted features, bf16 split ----------------
__global__ void k_gather(const float* __restrict__ f0, const float* __restrict__ f1,
                         const float* __restrict__ f2, const float* __restrict__ f3) {
    int i = blockIdx.x;
    if (i >= g_act_cnt) return;
    int tid = threadIdx.x;  // 256

    __shared__ int   soff[4];
    __shared__ float swg[4];
    if (tid < 4) {
        soff[tid] = g_act_off[tid * BN + i];
        swg[tid]  = g_act_wg[tid * BN + i];
    }
    __syncthreads();

    size_t rowb = (size_t)i * KF;
#pragma unroll
    for (int it = 0; it < KF / 256; it++) {
        int c = it * 256 + tid;
        const float* f; int cb, SS, m;
        if (c < 256)       { m = 0; cb = 0;    SS = 3136; f = f0; }
        else if (c < 768)  { m = 1; cb = 256;  SS = 784;  f = f1; }
        else if (c < 1792) { m = 2; cb = 768;  SS = 196;  f = f2; }
        else               { m = 3; cb = 1792; SS = 49;   f = f3; }
        float v = swg[m] * __ldg(f + (size_t)soff[m] + (size_t)(c - cb) * SS);
        __nv_bfloat16 hi = __float2bfloat16(v);
        g_fhi[rowb + c] = hi;
        g_flo[rowb + c] = __float2bfloat16(v - __bfloat162float(hi));
    }
}

// ---------------- build stage-0 X split directly (no k_fill); reset g_act_cnt ----------------
__global__ void k_split(const float* __restrict__ lin_b,
                        const float* __restrict__ feat,
                        const float* __restrict__ pos) {
    int idx = blockIdx.x * blockDim.x + threadIdx.x;
    if (idx == 0) g_act_cnt = 0;   // reset for next graph replay (k_prep reads it next launch)
    if (idx >= BN * KPAD) return;
    int v = idx / KPAD, c = idx % KPAD;
    float val = 0.f;
    if (c < 128) {
        val = lin_b[c];
        int s = g_slot[v];
        if (s >= 0) val += g_apart[(size_t)s * 128 + c];
    } else if (c < 256) {
        val = feat[v * 128 + (c - 128)];
    } else if (c < 259) {
        val = pos[v * 3 + (c - 256)];
    }
    __nv_bfloat16 hi = __float2bfloat16(val);
    g_ahi[idx] = hi;
    g_alo[idx] = __float2bfloat16(val - __bfloat162float(hi));
}

// ---------------- CSR build: warp/row, batched float2 + ballot compaction ----------------
__global__ void k_csr(const float* __restrict__ adj) {
    int warp = (blockIdx.x * blockDim.x + threadIdx.x) >> 5;
    if (warp >= BN) return;
    int lane = threadIdx.x & 31;
    int row = warp;
    int gb = (row / Nv) * Nv;
    const float* a = adj + (size_t)row * Nv;
    int* nb = &g_nbr[row * NBR_CAP];

    unsigned below = (1u << lane) - 1u;
    int base = 0;
    for (int it0 = 0; it0 < 40; it0 += 4) {
        float2 v[4];
#pragma unroll
        for (int u = 0; u < 4; u++) {
            int col = (it0 + u) * 64 + lane * 2;
            v[u] = make_float2(0.f, 0.f);
            if (col + 1 < Nv)      v[u] = *(const float2*)(a + col);
            else if (col < Nv)     v[u].x = a[col];
        }
#pragma unroll
        for (int u = 0; u < 4; u++) {
            int col = (it0 + u) * 64 + lane * 2;
            unsigned b0 = __ballot_sync(0xffffffffu, v[u].x != 0.f);
            unsigned b1 = __ballot_sync(0xffffffffu, v[u].y != 0.f);
            if (v[u].x != 0.f) {
                int p = base + __popc(b0 & below) + __popc(b1 & below);
                if (p < NBR_CAP) nb[p] = gb + col;
            }
            if (v[u].y != 0.f) {
                int p = base + __popc(b0 & (below | (1u << lane))) + __popc(b1 & below);
                if (p < NBR_CAP) nb[p] = gb + col + 1;
            }
            base += __popc(b0) + __popc(b1);
        }
    }
    if (lane == 0) g_ncnt[row] = min(base, NBR_CAP);
}

// ---------------- weight transpose + bf16 split (residual weights) ----------------
struct WPrep { const float* W[15]; int K[15]; };

__global__ void k_wprep(WPrep p) {
    int slab = blockIdx.y;
    int idx = blockIdx.x * blockDim.x + threadIdx.x;
    if (idx >= 128 * KPAD) return;
    int n = idx / KPAD, k = idx % KPAD;
    int K = p.K[slab];
    float w = (k < K) ? p.W[slab][(size_t)k * 128 + n] : 0.f;
    __nv_bfloat16 hi = __float2bfloat16(w);
    float lo = w - __bfloat162float(hi);
    g_wt_hi[(size_t)slab * 128 * KPAD + idx] = hi;
    g_wt_lo[(size_t)slab * 128 * KPAD + idx] = __float2bfloat16(lo);
}

// ---------------- lin_w transpose + bf16 split ----------------
__global__ void k_lwprep(const float* __restrict__ lin_w) {
    int idx = blockIdx.x * blockDim.x + threadIdx.x;
    if (idx >= 128 * KF) return;
    int n = idx / KF, k = idx % KF;
    float w = lin_w[(size_t)k * 128 + n];
    __nv_bfloat16 hi = __float2bfloat16(w);
    g_lw_hi[idx] = hi;
    g_lw_lo[idx] = __float2bfloat16(w - __bfloat162float(hi));
}

// ---------------- mma.sync bf16-split GEMM (pre-split A, cp.async, swizzled) ----------------
struct TcArgs {
    const __nv_bfloat16* Wh[3];
    const __nv_bfloat16* Wl[3];
    const float*         bias[3];
    float*               Y[3];
    int                  ldb;
    int                  dynM;   // if set, early-exit tiles past g_act_cnt
};

#define SA_HI 0
#define SA_LO 16384
#define SB_HI 32768
#define SB_LO 49152
#define SM_TOTAL 65536

__global__ __launch_bounds__(256, 2)
void k_mmagemm(const __nv_bfloat16* __restrict__ Ahi,
               const __nv_bfloat16* __restrict__ Alo,
               int lda, int nkb, TcArgs args) {
    int row0 = blockIdx.x * 128;
    if (args.dynM && row0 >= g_act_cnt) return;

    extern __shared__ char smem[];
    uint32_t sb = smem_u32(smem);
    int tid = threadIdx.x;
    int lane = tid & 31;
    int w = tid >> 5;
    int slab = blockIdx.y;
    int ldb = args.ldb;

    const __nv_bfloat16* Wh = args.Wh[slab];
    const __nv_bfloat16* Wl = args.Wl[slab];

    int mrow0 = (w >> 1) * 32;
    int ncol0 = (w & 1) * 64;

    int a_row = mrow0 + (lane & 7) + (lane & 8);
    uint32_t a_base = sb + (uint32_t)(a_row * 128);
    int a_sel = (lane >> 4) & 1;
    int a_r7 = a_row & 7;

    int b_n = ncol0 + (lane & 7) + ((lane & 16) ? 8 : 0);
    uint32_t b_base = sb + (uint32_t)(b_n * 128);
    int b_sel = (lane >> 3) & 1;
    int b_r7 = b_n & 7;

    int cr[4], cc[4];
    uint32_t cdst[4];
#pragma unroll
    for (int i = 0; i < 4; i++) {
        int e = tid + i * 256;
        cr[i] = e >> 3;
        cc[i] = e & 7;
        cdst[i] = (uint32_t)(cr[i] * 128 + ((cc[i] ^ (cr[i] & 7)) << 4));
    }

    float acc[2][8][4];
#pragma unroll
    for (int mt = 0; mt < 2; mt++)
#pragma unroll
        for (int nt = 0; nt < 8; nt++)
#pragma unroll
            for (int q = 0; q < 4; q++) acc[mt][nt][q] = 0.f;

    for (int kb = 0; kb < nkb; kb++) {
        int k0 = kb * 64;
#pragma unroll
        for (int i = 0; i < 4; i++) {
            int gr = row0 + cr[i];
            int ok = (gr < GM);
            size_t srcoff = (size_t)(ok ? gr : 0) * lda + k0 + cc[i] * 8;
            uint32_t sz = ok ? 16u : 0u;
            CP_ASYNC16(sb + SA_HI + cdst[i], Ahi + srcoff, sz);
            CP_ASYNC16(sb + SA_LO + cdst[i], Alo + srcoff, sz);
        }
#pragma unroll
        for (int i = 0; i < 4; i++) {
            size_t srcoff = (size_t)cr[i] * ldb + k0 + cc[i] * 8;
            CP_ASYNC16(sb + SB_HI + cdst[i], Wh + srcoff, 16u);
            CP_ASYNC16(sb + SB_LO + cdst[i], Wl + srcoff, 16u);
        }
        CP_COMMIT();
        CP_WAIT0();
        __syncthreads();

#pragma unroll
        for (int ks = 0; ks < 4; ks++) {
            uint32_t aco = (uint32_t)(((2 * ks + a_sel) ^ a_r7) << 4);
            uint32_t ah[2][4], al[2][4];
#pragma unroll
            for (int mt = 0; mt < 2; mt++) {
                uint32_t ao = (uint32_t)(mt * 2048) + aco;
                LDSM_X4(ah[mt][0], ah[mt][1], ah[mt][2], ah[mt][3], a_base + SA_HI + ao);
                LDSM_X4(al[mt][0], al[mt][1], al[mt][2], al[mt][3], a_base + SA_LO + ao);
            }
            uint32_t bco = (uint32_t)(((2 * ks + b_sel) ^ b_r7) << 4);
#pragma unroll
            for (int nt2 = 0; nt2 < 4; nt2++) {
                uint32_t bo = (uint32_t)(nt2 * 2048) + bco;
                uint32_t bh0, bh1, bh2, bh3, bl0, bl1, bl2, bl3;
                LDSM_X4(bh0, bh1, bh2, bh3, b_base + SB_HI + bo);
                LDSM_X4(bl0, bl1, bl2, bl3, b_base + SB_LO + bo);
#pragma unroll
                for (int mt = 0; mt < 2; mt++) {
                    mma_bf16(acc[mt][nt2 * 2],     ah[mt], bh0, bh1);
                    mma_bf16(acc[mt][nt2 * 2],     ah[mt], bl0, bl1);
                    mma_bf16(acc[mt][nt2 * 2],     al[mt], bh0, bh1);
                    mma_bf16(acc[mt][nt2 * 2 + 1], ah[mt], bh2, bh3);
                    mma_bf16(acc[mt][nt2 * 2 + 1], ah[mt], bl2, bl3);
                    mma_bf16(acc[mt][nt2 * 2 + 1], al[mt], bh2, bh3);
                }
            }
        }
        __syncthreads();
    }

    const float* bias = args.bias[slab];
    float* Y = args.Y[slab];
    int group = lane >> 2, tig = lane & 3;
#pragma unroll
    for (int mt = 0; mt < 2; mt++) {
        int r1 = row0 + mrow0 + mt * 16 + group;
        int r2 = r1 + 8;
#pragma unroll
        for (int nt = 0; nt < 8; nt++) {
            int c = ncol0 + nt * 8 + tig * 2;
            float b0 = bias ? bias[c] : 0.f;
            float b1 = bias ? bias[c + 1] : 0.f;
            if (r1 < GM) {
                Y[(size_t)r1 * 128 + c]     = acc[mt][nt][0] + b0;
                Y[(size_t)r1 * 128 + c + 1] = acc[mt][nt][1] + b1;
            }
            if (r2 < GM) {
                Y[(size_t)r2 * 128 + c]     = acc[mt][nt][2] + b0;
                Y[(size_t)r2 * 128 + c + 1] = acc[mt][nt][3] + b1;
            }
        }
    }
}

// ---------------- SpMM + relu (+skip); outputs bf16 split and/or fused 128->3 GEMM ----------------
__global__ void k_combine(const float* __restrict__ H, const float* __restrict__ T,
                          const float* __restrict__ S,
                          __nv_bfloat16* __restrict__ Ohi, __nv_bfloat16* __restrict__ Olo,
                          const float* __restrict__ W0, const float* __restrict__ W1) {
    int row = blockIdx.x * 8 + (threadIdx.x >> 5);
    if (row >= BN) return;
    int lane = threadIdx.x & 31;
    int cnt = g_ncnt[row];
    const int* nb = &g_nbr[row * NBR_CAP];
    size_t o = (size_t)row * 128 + lane * 4;
    float4 a = *(const float4*)&H[o];
    for (int k = 0; k < cnt; k++) {
        const float4 v = *(const float4*)&T[(size_t)nb[k] * 128 + lane * 4];
        a.x += v.x; a.y += v.y; a.z += v.z; a.w += v.w;
    }
    a.x = fmaxf(a.x, 0.f); a.y = fmaxf(a.y, 0.f);
    a.z = fmaxf(a.z, 0.f); a.w = fmaxf(a.w, 0.f);
    if (S) {
        const float4 s = *(const float4*)&S[o];
        a.x += s.x; a.y += s.y; a.z += s.z; a.w += s.w;
    }
    float vv[4] = {a.x, a.y, a.z, a.w};
    if (Ohi) {
        __nv_bfloat16 h[4], l[4];
#pragma unroll
        for (int q = 0; q < 4; q++) {
            h[q] = __float2bfloat16(vv[q]);
            l[q] = __float2bfloat16(vv[q] - __bfloat162float(h[q]));
        }
        uint2 hp, lp;
        memcpy(&hp, h, 8);
        memcpy(&lp, l, 8);
        *(uint2*)&Ohi[o] = hp;
        *(uint2*)&Olo[o] = lp;
    }
    if (W0) {  // fused final 128->3 double GEMM (warp-level reduction)
        float s6[6] = {0.f, 0.f, 0.f, 0.f, 0.f, 0.f};
#pragma unroll
        for (int q = 0; q < 4; q++) {
            int k = lane * 4 + q;
#pragma unroll
            for (int j = 0; j < 3; j++) {
                s6[j]     += vv[q] * W0[k * 3 + j];
                s6[3 + j] += vv[q] * W1[k * 3 + j];
            }
        }
#pragma unroll
        for (int off = 16; off > 0; off >>= 1)
#pragma unroll
            for (int i = 0; i < 6; i++)
                s6[i] += __shfl_xor_sync(0xffffffffu, s6[i], off);
        if (lane == 0) {
#pragma unroll
            for (int j = 0; j < 3; j++) {
                g_h3[row * 3 + j] = s6[j];
                g_t3[row * 3 + j] = s6[3 + j];
            }
        }
    }
}

// ---------------- final spmm + tanh(relu) + positions ----------------
__global__ void k_final(const float* __restrict__ pos, float* __restrict__ out) {
    int idx = blockIdx.x * blockDim.x + threadIdx.x;
    if (idx >= BN * 3) return;
    int row = idx / 3, j = idx % 3;
    int cnt = g_ncnt[row];
    const int* nb = &g_nbr[row * NBR_CAP];
    float acc = g_h3[idx];
    for (int k = 0; k < cnt; k++) acc += g_t3[(size_t)nb[k] * 3 + j];
    out[idx] = pos[idx] + tanhf(fmaxf(acc, 0.f));
}

// ---------------- launch ----------------
extern "C" void kernel_launch(void* const* d_in, const int* in_sizes, int n_in,
                              void* d_out, int out_size) {
    const float* conv0 = (const float*)d_in[0];
    const float* conv1 = (const float*)d_in[1];
    const float* conv2 = (const float*)d_in[2];
    const float* conv3 = (const float*)d_in[3];
    const float* pos   = (const float*)d_in[4];
    const float* feat  = (const float*)d_in[5];
    const float* adj   = (const float*)d_in[6];
    const float* lin_w = (const float*)d_in[7];
    const float* lin_b = (const float*)d_in[8];
    const float* rw[3][6];
    for (int r = 0; r < 3; r++)
        for (int k = 0; k < 6; k++)
            rw[r][k] = (const float*)d_in[9 + r * 6 + k];
    const float* gf_w0 = (const float*)d_in[27];
    const float* gf_w1 = (const float*)d_in[28];
    float* out = (float*)d_out;

    float *skip, *t, *h2, *hfloat, *apart;
    cudaGetSymbolAddress((void**)&skip, g_skip);
    cudaGetSymbolAddress((void**)&t, g_t);
    cudaGetSymbolAddress((void**)&h2, g_h2);
    cudaGetSymbolAddress((void**)&hfloat, g_hf);
    cudaGetSymbolAddress((void**)&apart, g_apart);
    __nv_bfloat16 *ahi, *alo, *hhi, *hlo, *ohi, *olo, *wthi, *wtlo, *lwhi, *lwlo, *fhi, *flo;
    cudaGetSymbolAddress((void**)&ahi, g_ahi);
    cudaGetSymbolAddress((void**)&alo, g_alo);
    cudaGetSymbolAddress((void**)&hhi, g_hhi);
    cudaGetSymbolAddress((void**)&hlo, g_hlo);
    cudaGetSymbolAddress((void**)&ohi, g_ohi);
    cudaGetSymbolAddress((void**)&olo, g_olo);
    cudaGetSymbolAddress((void**)&wthi, g_wt_hi);
    cudaGetSymbolAddress((void**)&wtlo, g_wt_lo);
    cudaGetSymbolAddress((void**)&lwhi, g_lw_hi);
    cudaGetSymbolAddress((void**)&lwlo, g_lw_lo);
    cudaGetSymbolAddress((void**)&fhi, g_fhi);
    cudaGetSymbolAddress((void**)&flo, g_flo);

    cudaFuncSetAttribute(k_mmagemm, cudaFuncAttributeMaxDynamicSharedMemorySize, SM_TOTAL);

    static cudaStream_t s_side = nullptr;
    static cudaEvent_t e_fork = nullptr, e_j1 = nullptr, e_j2 = nullptr;
    if (!s_side) {
        cudaStreamCreateWithFlags(&s_side, cudaStreamNonBlocking);
        cudaEventCreateWithFlags(&e_fork, cudaEventDisableTiming);
        cudaEventCreateWithFlags(&e_j1, cudaEventDisableTiming);
        cudaEventCreateWithFlags(&e_j2, cudaEventDisableTiming);
    }

    WPrep wp;
    const int Ks3[3] = {259, 128, 128};
    for (int rb = 0; rb < 3; rb++) {
        int cin = Ks3[rb];
        wp.W[rb * 5 + 0] = rw[rb][0]; wp.K[rb * 5 + 0] = cin;
        wp.W[rb * 5 + 1] = rw[rb][2]; wp.K[rb * 5 + 1] = cin;
        wp.W[rb * 5 + 2] = rw[rb][3]; wp.K[rb * 5 + 2] = cin;
        wp.W[rb * 5 + 3] = rw[rb][4]; wp.K[rb * 5 + 3] = 128;
        wp.W[rb * 5 + 4] = rw[rb][5]; wp.K[rb * 5 + 4] = 128;
    }

    // fork: lin_w prep first (needed earliest), then csr + residual wprep
    cudaEventRecord(e_fork, 0);
    cudaStreamWaitEvent(s_side, e_fork, 0);
    k_lwprep<<<(128 * KF + 255) / 256, 256, 0, s_side>>>(lin_w);
    cudaEventRecord(e_j1, s_side);
    k_csr<<<(BN * 32 + 255) / 256, 256, 0, s_side>>>(adj);
    k_wprep<<<dim3((128 * KPAD + 255) / 256, 15), 256, 0, s_side>>>(wp);
    cudaEventRecord(e_j2, s_side);

    // main: prep -> gather -> align GEMM -> split
    k_prep<<<(BN + 255) / 256, 256>>>(pos);
    k_gather<<<BN, 256>>>(conv0, conv1, conv2, conv3);

    cudaStreamWaitEvent(0, e_j1, 0);  // lin_w split ready
    TcArgs aa;
    aa.Wh[0] = lwhi; aa.Wl[0] = lwlo; aa.bias[0] = nullptr; aa.Y[0] = apart;
    aa.Wh[1] = lwhi; aa.Wl[1] = lwlo; aa.bias[1] = nullptr; aa.Y[1] = apart;  // unused
    aa.Wh[2] = lwhi; aa.Wl[2] = lwlo; aa.bias[2] = nullptr; aa.Y[2] = apart;  // unused
    aa.ldb = KF; aa.dynM = 1;
    k_mmagemm<<<dim3((GM + 127) / 128, 1), 256, SM_TOTAL>>>(fhi, flo, KF, KF / 64, aa);

    k_split<<<(BN * KPAD + 255) / 256, 256>>>(lin_b, feat, pos);

    const int RB = (GM + 127) / 128;  // 78 row tiles
    const int CB = (BN + 7) / 8;      // 1233 combine blocks
    const __nv_bfloat16* Ahis[3] = {ahi, ohi, ohi};
    const __nv_bfloat16* Alos[3] = {alo, olo, olo};
    const int ldas[3] = {KPAD, 128, 128};
    const int nkbs[3] = {5, 2, 2};

    cudaStreamWaitEvent(0, e_j2, 0);  // residual weights + csr ready

    for (int rb = 0; rb < 3; rb++) {
        TcArgs a1;
        a1.Wh[0] = wthi + (size_t)(rb * 5 + 0) * 128 * KPAD; a1.Wl[0] = wtlo + (size_t)(rb * 5 + 0) * 128 * KPAD;
        a1.Wh[1] = wthi + (size_t)(rb * 5 + 1) * 128 * KPAD; a1.Wl[1] = wtlo + (size_t)(rb * 5 + 1) * 128 * KPAD;
        a1.Wh[2] = wthi + (size_t)(rb * 5 + 2) * 128 * KPAD; a1.Wl[2] = wtlo + (size_t)(rb * 5 + 2) * 128 * KPAD;
        a1.bias[0] = rw[rb][1]; a1.Y[0] = skip;
        a1.bias[1] = nullptr;   a1.Y[1] = hfloat;
        a1.bias[2] = nullptr;   a1.Y[2] = t;
        a1.ldb = KPAD; a1.dynM = 0;
        k_mmagemm<<<dim3(RB, 3), 256, SM_TOTAL>>>(Ahis[rb], Alos[rb], ldas[rb], nkbs[rb], a1);
        k_combine<<<CB, 256>>>(hfloat, t, nullptr, hhi, hlo, nullptr, nullptr);

        TcArgs a2;
        a2.Wh[0] = wthi + (size_t)(rb * 5 + 3) * 128 * KPAD; a2.Wl[0] = wtlo + (size_t)(rb * 5 + 3) * 128 * KPAD;
        a2.Wh[1] = wthi + (size_t)(rb * 5 + 4) * 128 * KPAD; a2.Wl[1] = wtlo + (size_t)(rb * 5 + 4) * 128 * KPAD;
        a2.Wh[2] = a2.Wh[0]; a2.Wl[2] = a2.Wl[0];  // unused
        a2.bias[0] = nullptr; a2.Y[0] = h2;
        a2.bias[1] = nullptr; a2.Y[1] = t;
        a2.bias[2] = nullptr; a2.Y[2] = h2;        // unused
        a2.ldb = KPAD; a2.dynM = 0;
        k_mmagemm<<<dim3(RB, 2), 256, SM_TOTAL>>>(hhi, hlo, 128, 2, a2);
        bool last = (rb == 2);
        k_combine<<<CB, 256>>>(h2, t, skip,
                               last ? nullptr : ohi, last ? nullptr : olo,
                               last ? gf_w0 : nullptr, last ? gf_w1 : nullptr);
    }

    k_final<<<(BN * 3 + 255) / 256, 256>>>(pos, out);
}

// round 13
// speedup vs baseline: 1.2710x; 1.2710x over previous
#include <cuda_runtime.h>
#include <cuda_bf16.h>
#include <math.h>
#include <stdint.h>
#include <string.h>

#define Bc 4
#define Nv 2466
#define BN (Bc * Nv)          // 9864
#define NBR_CAP 96
#define GM BN
#define KPAD 320              // 5 K-blocks of 64 (max K=259)

// ---------------- scratch (device globals; no allocs) ----------------
__device__ float g_hf[BN * 128];   // float h scratch
__device__ float g_skip[BN * 128];
__device__ float g_t[BN * 128];
__device__ float g_h2[BN * 128];
__device__ float g_h3[BN * 3];
__device__ float g_t3[BN * 3];
__device__ int   g_nbr[BN * NBR_CAP];
__device__ int   g_ncnt[BN];
__device__ int   g_act_off[4 * BN];
__device__ float g_act_wg[4 * BN];
__device__ float g_apart[4 * BN * 128];
__device__ int   g_act_cnt;
__device__ int   g_slot[BN];
__device__ __nv_bfloat16 g_wt_hi[15 * 128 * KPAD];  // W^T [slab][n][k]
__device__ __nv_bfloat16 g_wt_lo[15 * 128 * KPAD];
__device__ __nv_bfloat16 g_ahi[BN * KPAD];          // stage-0 X split (zero-padded)
__device__ __nv_bfloat16 g_alo[BN * KPAD];
__device__ __nv_bfloat16 g_hhi[BN * 128];           // mid-stage h split
__device__ __nv_bfloat16 g_hlo[BN * 128];
__device__ __nv_bfloat16 g_ohi[BN * 128];           // stage-output split
__device__ __nv_bfloat16 g_olo[BN * 128];

// ---------------- helpers ----------------
__device__ __forceinline__ uint32_t smem_u32(const void* p) {
    uint32_t a;
    asm("{ .reg .u64 t; cvta.to.shared.u64 t, %1; cvt.u32.u64 %0, t; }" : "=r"(a) : "l"(p));
    return a;
}

#define LDSM_X4(r0, r1, r2, r3, addr)                                            \
    asm volatile("ldmatrix.sync.aligned.m8n8.x4.shared.b16 {%0,%1,%2,%3}, [%4];" \
        : "=r"(r0), "=r"(r1), "=r"(r2), "=r"(r3) : "r"(addr))

#define CP_ASYNC16(dst, src, sz)                                                 \
    asm volatile("cp.async.cg.shared.global [%0], [%1], 16, %2;"                 \
        :: "r"(dst), "l"(src), "r"(sz))
#define CP_COMMIT() asm volatile("cp.async.commit_group;")
#define CP_WAIT0()  asm volatile("cp.async.wait_group 0;")

__device__ __forceinline__ void mma_bf16(float* d, const uint32_t* a,
                                         uint32_t b0, uint32_t b1) {
    asm volatile(
        "mma.sync.aligned.m16n8k16.row.col.f32.bf16.bf16.f32 "
        "{%0,%1,%2,%3}, {%4,%5,%6,%7}, {%8,%9}, {%0,%1,%2,%3};"
        : "+f"(d[0]), "+f"(d[1]), "+f"(d[2]), "+f"(d[3])
        : "r"(a[0]), "r"(a[1]), "r"(a[2]), "r"(a[3]), "r"(b0), "r"(b1));
}

// ---------------- vertex projection / active-list build (resets g_slot) ----------------
__global__ void k_prep(const float* __restrict__ pos) {
    int v = blockIdx.x * blockDim.x + threadIdx.x;
    if (v >= BN) return;
    g_slot[v] = -1;
    int b = v / Nv;
    float px = pos[v * 3 + 0], py = pos[v * 3 + 1], pz = pos[v * 3 + 2];
    float h = 248.f * (py / pz) + 111.5f;
    h = fminf(fmaxf(h, 0.f), 223.f);
    float w = 248.f * (px / (-pz)) + 111.5f;
    w = fminf(fmaxf(w, 0.f), 223.f);

    const int   Ss[4] = {56, 28, 14, 7};
    const int   Cs[4] = {256, 512, 1024, 2048};
    const float rs[4] = {0.25f, 0.125f, 0.0625f, 0.03125f};

    int off[4]; float wg[4]; bool any = false;
#pragma unroll
    for (int m = 0; m < 4; m++) {
        int S = Ss[m];
        float x = h * rs[m], y = w * rs[m];
        int x1 = (int)floorf(x);
        int x2 = min((int)ceilf(x), S - 1);
        int y1 = (int)floorf(y);
        int y2 = min((int)ceilf(y), S - 1);
        int wi = (x2 - x1) * (y2 - y1);
        off[m] = b * Cs[m] * S * S + x1 * S + y1;
        wg[m] = (float)wi;
        any = any || (wi != 0);
    }
    if (any) {
        int slot = atomicAdd(&g_act_cnt, 1);
        g_slot[v] = slot;
#pragma unroll
        for (int m = 0; m < 4; m++) {
            g_act_off[m * BN + slot] = off[m];
            g_act_wg[m * BN + slot]  = wg[m];
        }
    }
}

// ---------------- sparse align: 8 vertices/block, pipelined gathers ----------------
__global__ void k_align_m(const float* __restrict__ f0, const float* __restrict__ f1,
                          const float* __restrict__ f2, const float* __restrict__ f3,
                          const float* __restrict__ lin_w) {
    int base = blockIdx.x * 8;
    int m = blockIdx.y;
    int cnt = g_act_cnt;
    if (base >= cnt) return;

    __shared__ float sval[2][8][32];
    __shared__ float sacc[8][128];
    __shared__ int   s_off[8];
    __shared__ float s_wg[8];

    int tid = threadIdx.x;
    int grp = tid >> 7;
    int j = tid & 127;
    if (tid < 8) {
        int i = base + tid;
        if (i < cnt) {
            s_off[tid] = g_act_off[m * BN + i];
            s_wg[tid]  = g_act_wg[m * BN + i];
        } else { s_off[tid] = 0; s_wg[tid] = 0.f; }
    }
    __syncthreads();

    const float* fs[4] = {f0, f1, f2, f3};
    const int Cs[4]     = {256, 512, 1024, 2048};
    const int SSs[4]    = {56 * 56, 28 * 28, 14 * 14, 7 * 7};
    const int cbase4[4] = {0, 256, 768, 1792};

    const float* f = fs[m];
    int SS = SSs[m], nch = Cs[m], cbase = cbase4[m];

    int r0 = (tid & 127) >> 5;
    int cl = tid & 31;
    size_t o0 = (size_t)s_off[r0]     + (size_t)cl * SS;
    size_t o1 = (size_t)s_off[r0 + 4] + (size_t)cl * SS;
    float w0 = s_wg[r0], w1 = s_wg[r0 + 4];

    float acc[8] = {0.f, 0.f, 0.f, 0.f, 0.f, 0.f, 0.f, 0.f};
    int c0 = grp * 32;
    float rg0 = w0 * __ldg(f + o0 + (size_t)c0 * SS);
    float rg1 = w1 * __ldg(f + o1 + (size_t)c0 * SS);

    for (; c0 < nch; c0 += 64) {
        sval[grp][r0][cl]     = rg0;
        sval[grp][r0 + 4][cl] = rg1;
        __syncthreads();
        int cn = c0 + 64;
        if (cn < nch) {
            rg0 = w0 * __ldg(f + o0 + (size_t)cn * SS);
            rg1 = w1 * __ldg(f + o1 + (size_t)cn * SS);
        }
        const float* wl = lin_w + (size_t)(cbase + c0) * 128 + j;
#pragma unroll
        for (int cc = 0; cc < 32; cc++) {
            float wv = wl[(size_t)cc * 128];
#pragma unroll
            for (int r = 0; r < 8; r++) acc[r] += sval[grp][r][cc] * wv;
        }
        __syncthreads();
    }
    if (grp == 1) {
#pragma unroll
        for (int r = 0; r < 8; r++) sacc[r][j] = acc[r];
    }
    __syncthreads();
    if (grp == 0) {
#pragma unroll
        for (int r = 0; r < 8; r++) {
            int i = base + r;
            if (i < cnt) g_apart[((size_t)m * BN + i) * 128 + j] = acc[r] + sacc[r][j];
        }
    }
}

// ---------------- build stage-0 X split directly; reset g_act_cnt ----------------
__global__ void k_split(const float* __restrict__ lin_b,
                        const float* __restrict__ feat,
                        const float* __restrict__ pos) {
    int idx = blockIdx.x * blockDim.x + threadIdx.x;
    if (idx == 0) g_act_cnt = 0;   // reset for next replay (all readers precede this kernel)
    if (idx >= BN * KPAD) return;
    int v = idx / KPAD, c = idx % KPAD;
    float val = 0.f;
    if (c < 128) {
        val = lin_b[c];
        int s = g_slot[v];
        if (s >= 0) {
            val += g_apart[((size_t)0 * BN + s) * 128 + c]
                 + g_apart[((size_t)1 * BN + s) * 128 + c]
                 + g_apart[((size_t)2 * BN + s) * 128 + c]
                 + g_apart[((size_t)3 * BN + s) * 128 + c];
        }
    } else if (c < 256) {
        val = feat[v * 128 + (c - 128)];
    } else if (c < 259) {
        val = pos[v * 3 + (c - 256)];
    }
    __nv_bfloat16 hi = __float2bfloat16(val);
    g_ahi[idx] = hi;
    g_alo[idx] = __float2bfloat16(val - __bfloat162float(hi));
}

// ---------------- CSR build: warp/row, batched float2 + ballot compaction ----------------
__global__ void k_csr(const float* __restrict__ adj) {
    int warp = (blockIdx.x * blockDim.x + threadIdx.x) >> 5;
    if (warp >= BN) return;
    int lane = threadIdx.x & 31;
    int row = warp;
    int gb = (row / Nv) * Nv;
    const float* a = adj + (size_t)row * Nv;
    int* nb = &g_nbr[row * NBR_CAP];

    unsigned below = (1u << lane) - 1u;
    int base = 0;
    for (int it0 = 0; it0 < 40; it0 += 4) {
        float2 v[4];
#pragma unroll
        for (int u = 0; u < 4; u++) {
            int col = (it0 + u) * 64 + lane * 2;
            v[u] = make_float2(0.f, 0.f);
            if (col + 1 < Nv)      v[u] = *(const float2*)(a + col);
            else if (col < Nv)     v[u].x = a[col];
        }
#pragma unroll
        for (int u = 0; u < 4; u++) {
            int col = (it0 + u) * 64 + lane * 2;
            unsigned b0 = __ballot_sync(0xffffffffu, v[u].x != 0.f);
            unsigned b1 = __ballot_sync(0xffffffffu, v[u].y != 0.f);
            if (v[u].x != 0.f) {
                int p = base + __popc(b0 & below) + __popc(b1 & below);
                if (p < NBR_CAP) nb[p] = gb + col;
            }
            if (v[u].y != 0.f) {
                int p = base + __popc(b0 & (below | (1u << lane))) + __popc(b1 & below);
                if (p < NBR_CAP) nb[p] = gb + col + 1;
            }
            base += __popc(b0) + __popc(b1);
        }
    }
    if (lane == 0) g_ncnt[row] = min(base, NBR_CAP);
}

// ---------------- weight transpose + bf16 split ----------------
struct WPrep { const float* W[15]; int K[15]; };

__global__ void k_wprep(WPrep p) {
    int slab = blockIdx.y;
    int idx = blockIdx.x * blockDim.x + threadIdx.x;
    if (idx >= 128 * KPAD) return;
    int n = idx / KPAD, k = idx % KPAD;
    int K = p.K[slab];
    float w = (k < K) ? p.W[slab][(size_t)k * 128 + n] : 0.f;
    __nv_bfloat16 hi = __float2bfloat16(w);
    float lo = w - __bfloat162float(hi);
    g_wt_hi[(size_t)slab * 128 * KPAD + idx] = hi;
    g_wt_lo[(size_t)slab * 128 * KPAD + idx] = __float2bfloat16(lo);
}

// ---------------- mma.sync bf16-split GEMM (pre-split A, cp.async, swizzled) ----------------
struct TcArgs {
    int          wslab[3];
    const float* bias[3];
    float*       Y[3];
};

#define SA_HI 0
#define SA_LO 16384
#define SB_HI 32768
#define SB_LO 49152
#define SM_TOTAL 65536

__global__ __launch_bounds__(256, 2)
void k_mmagemm(const __nv_bfloat16* __restrict__ Ahi,
               const __nv_bfloat16* __restrict__ Alo,
               int lda, int nkb, TcArgs args) {
    extern __shared__ char smem[];
    uint32_t sb = smem_u32(smem);
    int tid = threadIdx.x;
    int lane = tid & 31;
    int w = tid >> 5;
    int slab = blockIdx.y;
    int row0 = blockIdx.x * 128;

    const __nv_bfloat16* Wh = g_wt_hi + (size_t)args.wslab[slab] * 128 * KPAD;
    const __nv_bfloat16* Wl = g_wt_lo + (size_t)args.wslab[slab] * 128 * KPAD;

    int mrow0 = (w >> 1) * 32;
    int ncol0 = (w & 1) * 64;

    int a_row = mrow0 + (lane & 7) + (lane & 8);
    uint32_t a_base = sb + (uint32_t)(a_row * 128);
    int a_sel = (lane >> 4) & 1;
    int a_r7 = a_row & 7;

    int b_n = ncol0 + (lane & 7) + ((lane & 16) ? 8 : 0);
    uint32_t b_base = sb + (uint32_t)(b_n * 128);
    int b_sel = (lane >> 3) & 1;
    int b_r7 = b_n & 7;

    int cr[4], cc[4];
    uint32_t cdst[4];
#pragma unroll
    for (int i = 0; i < 4; i++) {
        int e = tid + i * 256;
        cr[i] = e >> 3;
        cc[i] = e & 7;
        cdst[i] = (uint32_t)(cr[i] * 128 + ((cc[i] ^ (cr[i] & 7)) << 4));
    }

    float acc[2][8][4];
#pragma unroll
    for (int mt = 0; mt < 2; mt++)
#pragma unroll
        for (int nt = 0; nt < 8; nt++)
#pragma unroll
            for (int q = 0; q < 4; q++) acc[mt][nt][q] = 0.f;

    for (int kb = 0; kb < nkb; kb++) {
        int k0 = kb * 64;
#pragma unroll
        for (int i = 0; i < 4; i++) {
            int gr = row0 + cr[i];
            int ok = (gr < GM);
            size_t srcoff = (size_t)(ok ? gr : 0) * lda + k0 + cc[i] * 8;
            uint32_t sz = ok ? 16u : 0u;
            CP_ASYNC16(sb + SA_HI + cdst[i], Ahi + srcoff, sz);
            CP_ASYNC16(sb + SA_LO + cdst[i], Alo + srcoff, sz);
        }
#pragma unroll
        for (int i = 0; i < 4; i++) {
            size_t srcoff = (size_t)cr[i] * KPAD + k0 + cc[i] * 8;
            CP_ASYNC16(sb + SB_HI + cdst[i], Wh + srcoff, 16u);
            CP_ASYNC16(sb + SB_LO + cdst[i], Wl + srcoff, 16u);
        }
        CP_COMMIT();
        CP_WAIT0();
        __syncthreads();

#pragma unroll
        for (int ks = 0; ks < 4; ks++) {
            uint32_t aco = (uint32_t)(((2 * ks + a_sel) ^ a_r7) << 4);
            uint32_t ah[2][4], al[2][4];
#pragma unroll
            for (int mt = 0; mt < 2; mt++) {
                uint32_t ao = (uint32_t)(mt * 2048) + aco;
                LDSM_X4(ah[mt][0], ah[mt][1], ah[mt][2], ah[mt][3], a_base + SA_HI + ao);
                LDSM_X4(al[mt][0], al[mt][1], al[mt][2], al[mt][3], a_base + SA_LO + ao);
            }
            uint32_t bco = (uint32_t)(((2 * ks + b_sel) ^ b_r7) << 4);
#pragma unroll
            for (int nt2 = 0; nt2 < 4; nt2++) {
                uint32_t bo = (uint32_t)(nt2 * 2048) + bco;
                uint32_t bh0, bh1, bh2, bh3, bl0, bl1, bl2, bl3;
                LDSM_X4(bh0, bh1, bh2, bh3, b_base + SB_HI + bo);
                LDSM_X4(bl0, bl1, bl2, bl3, b_base + SB_LO + bo);
#pragma unroll
                for (int mt = 0; mt < 2; mt++) {
                    mma_bf16(acc[mt][nt2 * 2],     ah[mt], bh0, bh1);
                    mma_bf16(acc[mt][nt2 * 2],     ah[mt], bl0, bl1);
                    mma_bf16(acc[mt][nt2 * 2],     al[mt], bh0, bh1);
                    mma_bf16(acc[mt][nt2 * 2 + 1], ah[mt], bh2, bh3);
                    mma_bf16(acc[mt][nt2 * 2 + 1], ah[mt], bl2, bl3);
                    mma_bf16(acc[mt][nt2 * 2 + 1], al[mt], bh2, bh3);
                }
            }
        }
        __syncthreads();
    }

    const float* bias = args.bias[slab];
    float* Y = args.Y[slab];
    int group = lane >> 2, tig = lane & 3;
#pragma unroll
    for (int mt = 0; mt < 2; mt++) {
        int r1 = row0 + mrow0 + mt * 16 + group;
        int r2 = r1 + 8;
#pragma unroll
        for (int nt = 0; nt < 8; nt++) {
            int c = ncol0 + nt * 8 + tig * 2;
            float b0 = bias ? bias[c] : 0.f;
            float b1 = bias ? bias[c + 1] : 0.f;
            if (r1 < GM) {
                Y[(size_t)r1 * 128 + c]     = acc[mt][nt][0] + b0;
                Y[(size_t)r1 * 128 + c + 1] = acc[mt][nt][1] + b1;
            }
            if (r2 < GM) {
                Y[(size_t)r2 * 128 + c]     = acc[mt][nt][2] + b0;
                Y[(size_t)r2 * 128 + c + 1] = acc[mt][nt][3] + b1;
            }
        }
    }
}

// ---------------- SpMM + relu (+skip); MLP-batched gathers; bf16 split / fused gemm3 ----------------
__global__ void k_combine(const float* __restrict__ H, const float* __restrict__ T,
                          const float* __restrict__ S,
                          __nv_bfloat16* __restrict__ Ohi, __nv_bfloat16* __restrict__ Olo,
                          const float* __restrict__ W0, const float* __restrict__ W1) {
    int row = blockIdx.x * 8 + (threadIdx.x >> 5);
    if (row >= BN) return;
    int lane = threadIdx.x & 31;
    int cnt = g_ncnt[row];
    const int* nb = &g_nbr[row * NBR_CAP];
    size_t o = (size_t)row * 128 + lane * 4;
    float4 a = *(const float4*)&H[o];
    int k = 0;
    for (; k + 4 <= cnt; k += 4) {   // 4 independent gathers in flight
        int n0 = nb[k], n1 = nb[k + 1], n2 = nb[k + 2], n3 = nb[k + 3];
        float4 v0 = *(const float4*)&T[(size_t)n0 * 128 + lane * 4];
        float4 v1 = *(const float4*)&T[(size_t)n1 * 128 + lane * 4];
        float4 v2 = *(const float4*)&T[(size_t)n2 * 128 + lane * 4];
        float4 v3 = *(const float4*)&T[(size_t)n3 * 128 + lane * 4];
        a.x += (v0.x + v1.x) + (v2.x + v3.x);
        a.y += (v0.y + v1.y) + (v2.y + v3.y);
        a.z += (v0.z + v1.z) + (v2.z + v3.z);
        a.w += (v0.w + v1.w) + (v2.w + v3.w);
    }
    for (; k < cnt; k++) {
        const float4 v = *(const float4*)&T[(size_t)nb[k] * 128 + lane * 4];
        a.x += v.x; a.y += v.y; a.z += v.z; a.w += v.w;
    }
    a.x = fmaxf(a.x, 0.f); a.y = fmaxf(a.y, 0.f);
    a.z = fmaxf(a.z, 0.f); a.w = fmaxf(a.w, 0.f);
    if (S) {
        const float4 s = *(const float4*)&S[o];
        a.x += s.x; a.y += s.y; a.z += s.z; a.w += s.w;
    }
    float vv[4] = {a.x, a.y, a.z, a.w};
    if (Ohi) {
        __nv_bfloat16 h[4], l[4];
#pragma unroll
        for (int q = 0; q < 4; q++) {
            h[q] = __float2bfloat16(vv[q]);
            l[q] = __float2bfloat16(vv[q] - __bfloat162float(h[q]));
        }
        uint2 hp, lp;
        memcpy(&hp, h, 8);
        memcpy(&lp, l, 8);
        *(uint2*)&Ohi[o] = hp;
        *(uint2*)&Olo[o] = lp;
    }
    if (W0) {  // fused final 128->3 double GEMM (warp-level reduction)
        float s6[6] = {0.f, 0.f, 0.f, 0.f, 0.f, 0.f};
#pragma unroll
        for (int q = 0; q < 4; q++) {
            int kk = lane * 4 + q;
#pragma unroll
            for (int j = 0; j < 3; j++) {
                s6[j]     += vv[q] * W0[kk * 3 + j];
                s6[3 + j] += vv[q] * W1[kk * 3 + j];
            }
        }
#pragma unroll
        for (int off = 16; off > 0; off >>= 1)
#pragma unroll
            for (int i = 0; i < 6; i++)
                s6[i] += __shfl_xor_sync(0xffffffffu, s6[i], off);
        if (lane == 0) {
#pragma unroll
            for (int j = 0; j < 3; j++) {
                g_h3[row * 3 + j] = s6[j];
                g_t3[row * 3 + j] = s6[3 + j];
            }
        }
    }
}

// ---------------- final spmm + tanh(relu) + positions ----------------
__global__ void k_final(const float* __restrict__ pos, float* __restrict__ out) {
    int idx = blockIdx.x * blockDim.x + threadIdx.x;
    if (idx >= BN * 3) return;
    int row = idx / 3, j = idx % 3;
    int cnt = g_ncnt[row];
    const int* nb = &g_nbr[row * NBR_CAP];
    float acc = g_h3[idx];
    for (int k = 0; k < cnt; k++) acc += g_t3[(size_t)nb[k] * 3 + j];
    out[idx] = pos[idx] + tanhf(fmaxf(acc, 0.f));
}

// ---------------- launch ----------------
extern "C" void kernel_launch(void* const* d_in, const int* in_sizes, int n_in,
                              void* d_out, int out_size) {
    const float* conv0 = (const float*)d_in[0];
    const float* conv1 = (const float*)d_in[1];
    const float* conv2 = (const float*)d_in[2];
    const float* conv3 = (const float*)d_in[3];
    const float* pos   = (const float*)d_in[4];
    const float* feat  = (const float*)d_in[5];
    const float* adj   = (const float*)d_in[6];
    const float* lin_w = (const float*)d_in[7];
    const float* lin_b = (const float*)d_in[8];
    const float* rw[3][6];
    for (int r = 0; r < 3; r++)
        for (int k = 0; k < 6; k++)
            rw[r][k] = (const float*)d_in[9 + r * 6 + k];
    const float* gf_w0 = (const float*)d_in[27];
    const float* gf_w1 = (const float*)d_in[28];
    float* out = (float*)d_out;

    float *skip, *t, *h2, *hfloat;
    cudaGetSymbolAddress((void**)&skip, g_skip);
    cudaGetSymbolAddress((void**)&t, g_t);
    cudaGetSymbolAddress((void**)&h2, g_h2);
    cudaGetSymbolAddress((void**)&hfloat, g_hf);
    __nv_bfloat16 *ahi, *alo, *hhi, *hlo, *ohi, *olo;
    cudaGetSymbolAddress((void**)&ahi, g_ahi);
    cudaGetSymbolAddress((void**)&alo, g_alo);
    cudaGetSymbolAddress((void**)&hhi, g_hhi);
    cudaGetSymbolAddress((void**)&hlo, g_hlo);
    cudaGetSymbolAddress((void**)&ohi, g_ohi);
    cudaGetSymbolAddress((void**)&olo, g_olo);

    cudaFuncSetAttribute(k_mmagemm, cudaFuncAttributeMaxDynamicSharedMemorySize, SM_TOTAL);

    static cudaStream_t s_side = nullptr;
    static cudaEvent_t e_fork = nullptr, e_join = nullptr;
    if (!s_side) {
        cudaStreamCreateWithFlags(&s_side, cudaStreamNonBlocking);
        cudaEventCreateWithFlags(&e_fork, cudaEventDisableTiming);
        cudaEventCreateWithFlags(&e_join, cudaEventDisableTiming);
    }

    WPrep wp;
    const int Ks3[3] = {259, 128, 128};
    for (int rb = 0; rb < 3; rb++) {
        int cin = Ks3[rb];
        wp.W[rb * 5 + 0] = rw[rb][0]; wp.K[rb * 5 + 0] = cin;
        wp.W[rb * 5 + 1] = rw[rb][2]; wp.K[rb * 5 + 1] = cin;
        wp.W[rb * 5 + 2] = rw[rb][3]; wp.K[rb * 5 + 2] = cin;
        wp.W[rb * 5 + 3] = rw[rb][4]; wp.K[rb * 5 + 3] = 128;
        wp.W[rb * 5 + 4] = rw[rb][5]; wp.K[rb * 5 + 4] = 128;
    }

    // fork: csr + wprep on the side stream
    cudaEventRecord(e_fork, 0);
    cudaStreamWaitEvent(s_side, e_fork, 0);
    k_csr<<<(BN * 32 + 255) / 256, 256, 0, s_side>>>(adj);
    k_wprep<<<dim3((128 * KPAD + 255) / 256, 15), 256, 0, s_side>>>(wp);
    cudaEventRecord(e_join, s_side);

    k_prep<<<(BN + 255) / 256, 256>>>(pos);   // resets g_slot, builds active list
    k_align_m<<<dim3((BN + 7) / 8, 4), 256>>>(conv0, conv1, conv2, conv3, lin_w);
    k_split<<<(BN * KPAD + 255) / 256, 256>>>(lin_b, feat, pos);  // concat+align-reduce+split

    const int RB = (GM + 127) / 128;  // 78 row tiles
    const int CB = (BN + 7) / 8;      // 1233 combine blocks
    const __nv_bfloat16* Ahis[3] = {ahi, ohi, ohi};
    const __nv_bfloat16* Alos[3] = {alo, olo, olo};
    const int ldas[3] = {KPAD, 128, 128};
    const int nkbs[3] = {5, 2, 2};

    cudaStreamWaitEvent(0, e_join, 0);

    for (int rb = 0; rb < 3; rb++) {
        TcArgs a1;
        a1.wslab[0] = rb * 5 + 0; a1.bias[0] = rw[rb][1]; a1.Y[0] = skip;
        a1.wslab[1] = rb * 5 + 1; a1.bias[1] = nullptr;   a1.Y[1] = hfloat;
        a1.wslab[2] = rb * 5 + 2; a1.bias[2] = nullptr;   a1.Y[2] = t;
        k_mmagemm<<<dim3(RB, 3), 256, SM_TOTAL>>>(Ahis[rb], Alos[rb], ldas[rb], nkbs[rb], a1);
        k_combine<<<CB, 256>>>(hfloat, t, nullptr, hhi, hlo, nullptr, nullptr);

        TcArgs a2;
        a2.wslab[0] = rb * 5 + 3; a2.bias[0] = nullptr; a2.Y[0] = h2;
        a2.wslab[1] = rb * 5 + 4; a2.bias[1] = nullptr; a2.Y[1] = t;
        a2.wslab[2] = rb * 5 + 3; a2.bias[2] = nullptr; a2.Y[2] = h2;  // unused
        k_mmagemm<<<dim3(RB, 2), 256, SM_TOTAL>>>(hhi, hlo, 128, 2, a2);
        bool last = (rb == 2);
        k_combine<<<CB, 256>>>(h2, t, skip,
                               last ? nullptr : ohi, last ? nullptr : olo,
                               last ? gf_w0 : nullptr, last ? gf_w1 : nullptr);
    }

    k_final<<<(BN * 3 + 255) / 256, 256>>>(pos, out);
}

// round 14
// speedup vs baseline: 1.4891x; 1.1716x over previous
#include <cuda_runtime.h>
#include <cuda_bf16.h>
#include <math.h>
#include <stdint.h>
#include <string.h>

#define Bc 4
#define Nv 2466
#define BN (Bc * Nv)          // 9864
#define NBR_CAP 96
#define GM BN
#define KPAD 320              // 5 K-blocks of 64 (max K=259)
#define NSLAB 15              // align channel slabs of 256

// ---------------- scratch (device globals; no allocs) ----------------
__device__ float g_hf[BN * 128];   // float h scratch
__device__ float g_skip[BN * 128];
__device__ float g_t[BN * 128];
__device__ float g_h2[BN * 128];
__device__ float g_h3[BN * 3];
__device__ float g_t3[BN * 3];
__device__ int   g_nbr[BN * NBR_CAP];
__device__ int   g_ncnt[BN];
__device__ int   g_act_off[4 * BN];
__device__ float g_act_wg[4 * BN];
__device__ float g_apart[NSLAB * BN * 128];
__device__ int   g_act_cnt;
__device__ int   g_slot[BN];
__device__ __nv_bfloat16 g_wt_hi[15 * 128 * KPAD];  // W^T [slab][n][k]
__device__ __nv_bfloat16 g_wt_lo[15 * 128 * KPAD];
__device__ __nv_bfloat16 g_ahi[BN * KPAD];          // stage-0 X split (zero-padded)
__device__ __nv_bfloat16 g_alo[BN * KPAD];
__device__ __nv_bfloat16 g_hhi[BN * 128];           // mid-stage h split
__device__ __nv_bfloat16 g_hlo[BN * 128];
__device__ __nv_bfloat16 g_ohi[BN * 128];           // stage-output split
__device__ __nv_bfloat16 g_olo[BN * 128];

// ---------------- helpers ----------------
__device__ __forceinline__ uint32_t smem_u32(const void* p) {
    uint32_t a;
    asm("{ .reg .u64 t; cvta.to.shared.u64 t, %1; cvt.u32.u64 %0, t; }" : "=r"(a) : "l"(p));
    return a;
}

#define LDSM_X4(r0, r1, r2, r3, addr)                                            \
    asm volatile("ldmatrix.sync.aligned.m8n8.x4.shared.b16 {%0,%1,%2,%3}, [%4];" \
        : "=r"(r0), "=r"(r1), "=r"(r2), "=r"(r3) : "r"(addr))

#define CP_ASYNC16(dst, src, sz)                                                 \
    asm volatile("cp.async.cg.shared.global [%0], [%1], 16, %2;"                 \
        :: "r"(dst), "l"(src), "r"(sz))
#define CP_COMMIT() asm volatile("cp.async.commit_group;")
#define CP_WAIT0()  asm volatile("cp.async.wait_group 0;")

__device__ __forceinline__ void mma_bf16(float* d, const uint32_t* a,
                                         uint32_t b0, uint32_t b1) {
    asm volatile(
        "mma.sync.aligned.m16n8k16.row.col.f32.bf16.bf16.f32 "
        "{%0,%1,%2,%3}, {%4,%5,%6,%7}, {%8,%9}, {%0,%1,%2,%3};"
        : "+f"(d[0]), "+f"(d[1]), "+f"(d[2]), "+f"(d[3])
        : "r"(a[0]), "r"(a[1]), "r"(a[2]), "r"(a[3]), "r"(b0), "r"(b1));
}

// ---------------- vertex projection / active-list build (resets g_slot) ----------------
__global__ void k_prep(const float* __restrict__ pos) {
    int v = blockIdx.x * blockDim.x + threadIdx.x;
    if (v >= BN) return;
    g_slot[v] = -1;
    int b = v / Nv;
    float px = pos[v * 3 + 0], py = pos[v * 3 + 1], pz = pos[v * 3 + 2];
    float h = 248.f * (py / pz) + 111.5f;
    h = fminf(fmaxf(h, 0.f), 223.f);
    float w = 248.f * (px / (-pz)) + 111.5f;
    w = fminf(fmaxf(w, 0.f), 223.f);

    const int   Ss[4] = {56, 28, 14, 7};
    const int   Cs[4] = {256, 512, 1024, 2048};
    const float rs[4] = {0.25f, 0.125f, 0.0625f, 0.03125f};

    int off[4]; float wg[4]; bool any = false;
#pragma unroll
    for (int m = 0; m < 4; m++) {
        int S = Ss[m];
        float x = h * rs[m], y = w * rs[m];
        int x1 = (int)floorf(x);
        int x2 = min((int)ceilf(x), S - 1);
        int y1 = (int)floorf(y);
        int y2 = min((int)ceilf(y), S - 1);
        int wi = (x2 - x1) * (y2 - y1);
        off[m] = b * Cs[m] * S * S + x1 * S + y1;
        wg[m] = (float)wi;
        any = any || (wi != 0);
    }
    if (any) {
        int slot = atomicAdd(&g_act_cnt, 1);
        g_slot[v] = slot;
#pragma unroll
        for (int m = 0; m < 4; m++) {
            g_act_off[m * BN + slot] = off[m];
            g_act_wg[m * BN + slot]  = wg[m];
        }
    }
}

// ---------------- sparse align: 8 vertices/block, 15 channel slabs of 256 ----------------
__global__ void k_align_m(const float* __restrict__ f0, const float* __restrict__ f1,
                          const float* __restrict__ f2, const float* __restrict__ f3,
                          const float* __restrict__ lin_w) {
    int base = blockIdx.x * 8;
    int slab = blockIdx.y;
    int cnt = g_act_cnt;
    if (base >= cnt) return;

    // slab -> (feature map, channel offset within map)
    const int ms[NSLAB]    = {0, 1, 1, 2, 2, 2, 2, 3, 3, 3, 3, 3, 3, 3, 3};
    const int coffs[NSLAB] = {0, 0, 256, 0, 256, 512, 768,
                              0, 256, 512, 768, 1024, 1280, 1536, 1792};
    int m = ms[slab];
    int coff = coffs[slab];

    __shared__ float sval[2][8][32];
    __shared__ float sacc[8][128];
    __shared__ int   s_off[8];
    __shared__ float s_wg[8];

    int tid = threadIdx.x;
    int grp = tid >> 7;
    int j = tid & 127;
    if (tid < 8) {
        int i = base + tid;
        if (i < cnt) {
            s_off[tid] = g_act_off[m * BN + i];
            s_wg[tid]  = g_act_wg[m * BN + i];
        } else { s_off[tid] = 0; s_wg[tid] = 0.f; }
    }
    __syncthreads();

    const float* fs[4] = {f0, f1, f2, f3};
    const int SSs[4]    = {56 * 56, 28 * 28, 14 * 14, 7 * 7};
    const int cbase4[4] = {0, 256, 768, 1792};

    const float* f = fs[m];
    int SS = SSs[m];
    int cbase = cbase4[m] + coff;    // global channel base for lin_w row index
    int cend = coff + 256;

    int r0 = (tid & 127) >> 5;
    int cl = tid & 31;
    size_t o0 = (size_t)s_off[r0]     + (size_t)cl * SS;
    size_t o1 = (size_t)s_off[r0 + 4] + (size_t)cl * SS;
    float w0 = s_wg[r0], w1 = s_wg[r0 + 4];

    float acc[8] = {0.f, 0.f, 0.f, 0.f, 0.f, 0.f, 0.f, 0.f};
    int c0 = coff + grp * 32;
    float rg0 = w0 * __ldg(f + o0 + (size_t)c0 * SS);
    float rg1 = w1 * __ldg(f + o1 + (size_t)c0 * SS);

    for (; c0 < cend; c0 += 64) {
        sval[grp][r0][cl]     = rg0;
        sval[grp][r0 + 4][cl] = rg1;
        __syncthreads();
        int cn = c0 + 64;
        if (cn < cend) {
            rg0 = w0 * __ldg(f + o0 + (size_t)cn * SS);
            rg1 = w1 * __ldg(f + o1 + (size_t)cn * SS);
        }
        const float* wl = lin_w + (size_t)(cbase + (c0 - coff)) * 128 + j;
#pragma unroll
        for (int cc = 0; cc < 32; cc++) {
            float wv = wl[(size_t)cc * 128];
#pragma unroll
            for (int r = 0; r < 8; r++) acc[r] += sval[grp][r][cc] * wv;
        }
        __syncthreads();
    }
    if (grp == 1) {
#pragma unroll
        for (int r = 0; r < 8; r++) sacc[r][j] = acc[r];
    }
    __syncthreads();
    if (grp == 0) {
#pragma unroll
        for (int r = 0; r < 8; r++) {
            int i = base + r;
            if (i < cnt) g_apart[((size_t)slab * BN + i) * 128 + j] = acc[r] + sacc[r][j];
        }
    }
}

// ---------------- build stage-0 X split directly; reset g_act_cnt ----------------
__global__ void k_split(const float* __restrict__ lin_b,
                        const float* __restrict__ feat,
                        const float* __restrict__ pos) {
    int idx = blockIdx.x * blockDim.x + threadIdx.x;
    if (idx == 0) g_act_cnt = 0;   // reset for next replay (all readers precede this kernel)
    if (idx >= BN * KPAD) return;
    int v = idx / KPAD, c = idx % KPAD;
    float val = 0.f;
    if (c < 128) {
        val = lin_b[c];
        int s = g_slot[v];
        if (s >= 0) {
            float acc = 0.f;
#pragma unroll
            for (int sl = 0; sl < NSLAB; sl++)
                acc += g_apart[((size_t)sl * BN + s) * 128 + c];
            val += acc;
        }
    } else if (c < 256) {
        val = feat[v * 128 + (c - 128)];
    } else if (c < 259) {
        val = pos[v * 3 + (c - 256)];
    }
    __nv_bfloat16 hi = __float2bfloat16(val);
    g_ahi[idx] = hi;
    g_alo[idx] = __float2bfloat16(val - __bfloat162float(hi));
}

// ---------------- CSR build: warp/row, batched float2 + ballot compaction ----------------
__global__ void k_csr(const float* __restrict__ adj) {
    int warp = (blockIdx.x * blockDim.x + threadIdx.x) >> 5;
    if (warp >= BN) return;
    int lane = threadIdx.x & 31;
    int row = warp;
    int gb = (row / Nv) * Nv;
    const float* a = adj + (size_t)row * Nv;
    int* nb = &g_nbr[row * NBR_CAP];

    unsigned below = (1u << lane) - 1u;
    int base = 0;
    for (int it0 = 0; it0 < 40; it0 += 4) {
        float2 v[4];
#pragma unroll
        for (int u = 0; u < 4; u++) {
            int col = (it0 + u) * 64 + lane * 2;
            v[u] = make_float2(0.f, 0.f);
            if (col + 1 < Nv)      v[u] = *(const float2*)(a + col);
            else if (col < Nv)     v[u].x = a[col];
        }
#pragma unroll
        for (int u = 0; u < 4; u++) {
            int col = (it0 + u) * 64 + lane * 2;
            unsigned b0 = __ballot_sync(0xffffffffu, v[u].x != 0.f);
            unsigned b1 = __ballot_sync(0xffffffffu, v[u].y != 0.f);
            if (v[u].x != 0.f) {
                int p = base + __popc(b0 & below) + __popc(b1 & below);
                if (p < NBR_CAP) nb[p] = gb + col;
            }
            if (v[u].y != 0.f) {
                int p = base + __popc(b0 & (below | (1u << lane))) + __popc(b1 & below);
                if (p < NBR_CAP) nb[p] = gb + col + 1;
            }
            base += __popc(b0) + __popc(b1);
        }
    }
    if (lane == 0) g_ncnt[row] = min(base, NBR_CAP);
}

// ---------------- weight transpose + bf16 split ----------------
struct WPrep { const float* W[15]; int K[15]; };

__global__ void k_wprep(WPrep p) {
    int slab = blockIdx.y;
    int idx = blockIdx.x * blockDim.x + threadIdx.x;
    if (idx >= 128 * KPAD) return;
    int n = idx / KPAD, k = idx % KPAD;
    int K = p.K[slab];
    float w = (k < K) ? p.W[slab][(size_t)k * 128 + n] : 0.f;
    __nv_bfloat16 hi = __float2bfloat16(w);
    float lo = w - __bfloat162float(hi);
    g_wt_hi[(size_t)slab * 128 * KPAD + idx] = hi;
    g_wt_lo[(size_t)slab * 128 * KPAD + idx] = __float2bfloat16(lo);
}

// ---------------- mma.sync bf16-split GEMM (pre-split A, cp.async, swizzled) ----------------
struct TcArgs {
    int          wslab[3];
    const float* bias[3];
    float*       Y[3];
};

#define SA_HI 0
#define SA_LO 16384
#define SB_HI 32768
#define SB_LO 49152
#define SM_TOTAL 65536

__global__ __launch_bounds__(256, 2)
void k_mmagemm(const __nv_bfloat16* __restrict__ Ahi,
               const __nv_bfloat16* __restrict__ Alo,
               int lda, int nkb, TcArgs args) {
    extern __shared__ char smem[];
    uint32_t sb = smem_u32(smem);
    int tid = threadIdx.x;
    int lane = tid & 31;
    int w = tid >> 5;
    int slab = blockIdx.y;
    int row0 = blockIdx.x * 128;

    const __nv_bfloat16* Wh = g_wt_hi + (size_t)args.wslab[slab] * 128 * KPAD;
    const __nv_bfloat16* Wl = g_wt_lo + (size_t)args.wslab[slab] * 128 * KPAD;

    int mrow0 = (w >> 1) * 32;
    int ncol0 = (w & 1) * 64;

    int a_row = mrow0 + (lane & 7) + (lane & 8);
    uint32_t a_base = sb + (uint32_t)(a_row * 128);
    int a_sel = (lane >> 4) & 1;
    int a_r7 = a_row & 7;

    int b_n = ncol0 + (lane & 7) + ((lane & 16) ? 8 : 0);
    uint32_t b_base = sb + (uint32_t)(b_n * 128);
    int b_sel = (lane >> 3) & 1;
    int b_r7 = b_n & 7;

    int cr[4], cc[4];
    uint32_t cdst[4];
#pragma unroll
    for (int i = 0; i < 4; i++) {
        int e = tid + i * 256;
        cr[i] = e >> 3;
        cc[i] = e & 7;
        cdst[i] = (uint32_t)(cr[i] * 128 + ((cc[i] ^ (cr[i] & 7)) << 4));
    }

    float acc[2][8][4];
#pragma unroll
    for (int mt = 0; mt < 2; mt++)
#pragma unroll
        for (int nt = 0; nt < 8; nt++)
#pragma unroll
            for (int q = 0; q < 4; q++) acc[mt][nt][q] = 0.f;

    for (int kb = 0; kb < nkb; kb++) {
        int k0 = kb * 64;
#pragma unroll
        for (int i = 0; i < 4; i++) {
            int gr = row0 + cr[i];
            int ok = (gr < GM);
            size_t srcoff = (size_t)(ok ? gr : 0) * lda + k0 + cc[i] * 8;
            uint32_t sz = ok ? 16u : 0u;
            CP_ASYNC16(sb + SA_HI + cdst[i], Ahi + srcoff, sz);
            CP_ASYNC16(sb + SA_LO + cdst[i], Alo + srcoff, sz);
        }
#pragma unroll
        for (int i = 0; i < 4; i++) {
            size_t srcoff = (size_t)cr[i] * KPAD + k0 + cc[i] * 8;
            CP_ASYNC16(sb + SB_HI + cdst[i], Wh + srcoff, 16u);
            CP_ASYNC16(sb + SB_LO + cdst[i], Wl + srcoff, 16u);
        }
        CP_COMMIT();
        CP_WAIT0();
        __syncthreads();

#pragma unroll
        for (int ks = 0; ks < 4; ks++) {
            uint32_t aco = (uint32_t)(((2 * ks + a_sel) ^ a_r7) << 4);
            uint32_t ah[2][4], al[2][4];
#pragma unroll
            for (int mt = 0; mt < 2; mt++) {
                uint32_t ao = (uint32_t)(mt * 2048) + aco;
                LDSM_X4(ah[mt][0], ah[mt][1], ah[mt][2], ah[mt][3], a_base + SA_HI + ao);
                LDSM_X4(al[mt][0], al[mt][1], al[mt][2], al[mt][3], a_base + SA_LO + ao);
            }
            uint32_t bco = (uint32_t)(((2 * ks + b_sel) ^ b_r7) << 4);
#pragma unroll
            for (int nt2 = 0; nt2 < 4; nt2++) {
                uint32_t bo = (uint32_t)(nt2 * 2048) + bco;
                uint32_t bh0, bh1, bh2, bh3, bl0, bl1, bl2, bl3;
                LDSM_X4(bh0, bh1, bh2, bh3, b_base + SB_HI + bo);
                LDSM_X4(bl0, bl1, bl2, bl3, b_base + SB_LO + bo);
#pragma unroll
                for (int mt = 0; mt < 2; mt++) {
                    mma_bf16(acc[mt][nt2 * 2],     ah[mt], bh0, bh1);
                    mma_bf16(acc[mt][nt2 * 2],     ah[mt], bl0, bl1);
                    mma_bf16(acc[mt][nt2 * 2],     al[mt], bh0, bh1);
                    mma_bf16(acc[mt][nt2 * 2 + 1], ah[mt], bh2, bh3);
                    mma_bf16(acc[mt][nt2 * 2 + 1], ah[mt], bl2, bl3);
                    mma_bf16(acc[mt][nt2 * 2 + 1], al[mt], bh2, bh3);
                }
            }
        }
        __syncthreads();
    }

    const float* bias = args.bias[slab];
    float* Y = args.Y[slab];
    int group = lane >> 2, tig = lane & 3;
#pragma unroll
    for (int mt = 0; mt < 2; mt++) {
        int r1 = row0 + mrow0 + mt * 16 + group;
        int r2 = r1 + 8;
#pragma unroll
        for (int nt = 0; nt < 8; nt++) {
            int c = ncol0 + nt * 8 + tig * 2;
            float b0 = bias ? bias[c] : 0.f;
            float b1 = bias ? bias[c + 1] : 0.f;
            if (r1 < GM) {
                Y[(size_t)r1 * 128 + c]     = acc[mt][nt][0] + b0;
                Y[(size_t)r1 * 128 + c + 1] = acc[mt][nt][1] + b1;
            }
            if (r2 < GM) {
                Y[(size_t)r2 * 128 + c]     = acc[mt][nt][2] + b0;
                Y[(size_t)r2 * 128 + c + 1] = acc[mt][nt][3] + b1;
            }
        }
    }
}

// ---------------- SpMM + relu (+skip); MLP-batched gathers; bf16 split / fused gemm3 ----------------
__global__ void k_combine(const float* __restrict__ H, const float* __restrict__ T,
                          const float* __restrict__ S,
                          __nv_bfloat16* __restrict__ Ohi, __nv_bfloat16* __restrict__ Olo,
                          const float* __restrict__ W0, const float* __restrict__ W1) {
    int row = blockIdx.x * 8 + (threadIdx.x >> 5);
    if (row >= BN) return;
    int lane = threadIdx.x & 31;
    int cnt = g_ncnt[row];
    const int* nb = &g_nbr[row * NBR_CAP];
    size_t o = (size_t)row * 128 + lane * 4;
    float4 a = *(const float4*)&H[o];
    int k = 0;
    for (; k + 4 <= cnt; k += 4) {   // 4 independent gathers in flight
        int n0 = nb[k], n1 = nb[k + 1], n2 = nb[k + 2], n3 = nb[k + 3];
        float4 v0 = *(const float4*)&T[(size_t)n0 * 128 + lane * 4];
        float4 v1 = *(const float4*)&T[(size_t)n1 * 128 + lane * 4];
        float4 v2 = *(const float4*)&T[(size_t)n2 * 128 + lane * 4];
        float4 v3 = *(const float4*)&T[(size_t)n3 * 128 + lane * 4];
        a.x += (v0.x + v1.x) + (v2.x + v3.x);
        a.y += (v0.y + v1.y) + (v2.y + v3.y);
        a.z += (v0.z + v1.z) + (v2.z + v3.z);
        a.w += (v0.w + v1.w) + (v2.w + v3.w);
    }
    for (; k < cnt; k++) {
        const float4 v = *(const float4*)&T[(size_t)nb[k] * 128 + lane * 4];
        a.x += v.x; a.y += v.y; a.z += v.z; a.w += v.w;
    }
    a.x = fmaxf(a.x, 0.f); a.y = fmaxf(a.y, 0.f);
    a.z = fmaxf(a.z, 0.f); a.w = fmaxf(a.w, 0.f);
    if (S) {
        const float4 s = *(const float4*)&S[o];
        a.x += s.x; a.y += s.y; a.z += s.z; a.w += s.w;
    }
    float vv[4] = {a.x, a.y, a.z, a.w};
    if (Ohi) {
        __nv_bfloat16 h[4], l[4];
#pragma unroll
        for (int q = 0; q < 4; q++) {
            h[q] = __float2bfloat16(vv[q]);
            l[q] = __float2bfloat16(vv[q] - __bfloat162float(h[q]));
        }
        uint2 hp, lp;
        memcpy(&hp, h, 8);
        memcpy(&lp, l, 8);
        *(uint2*)&Ohi[o] = hp;
        *(uint2*)&Olo[o] = lp;
    }
    if (W0) {  // fused final 128->3 double GEMM (warp-level reduction)
        float s6[6] = {0.f, 0.f, 0.f, 0.f, 0.f, 0.f};
#pragma unroll
        for (int q = 0; q < 4; q++) {
            int kk = lane * 4 + q;
#pragma unroll
            for (int j = 0; j < 3; j++) {
                s6[j]     += vv[q] * W0[kk * 3 + j];
                s6[3 + j] += vv[q] * W1[kk * 3 + j];
            }
        }
#pragma unroll
        for (int off = 16; off > 0; off >>= 1)
#pragma unroll
            for (int i = 0; i < 6; i++)
                s6[i] += __shfl_xor_sync(0xffffffffu, s6[i], off);
        if (lane == 0) {
#pragma unroll
            for (int j = 0; j < 3; j++) {
                g_h3[row * 3 + j] = s6[j];
                g_t3[row * 3 + j] = s6[3 + j];
            }
        }
    }
}

// ---------------- final spmm + tanh(relu) + positions ----------------
__global__ void k_final(const float* __restrict__ pos, float* __restrict__ out) {
    int idx = blockIdx.x * blockDim.x + threadIdx.x;
    if (idx >= BN * 3) return;
    int row = idx / 3, j = idx % 3;
    int cnt = g_ncnt[row];
    const int* nb = &g_nbr[row * NBR_CAP];
    float acc = g_h3[idx];
    for (int k = 0; k < cnt; k++) acc += g_t3[(size_t)nb[k] * 3 + j];
    out[idx] = pos[idx] + tanhf(fmaxf(acc, 0.f));
}

// ---------------- launch ----------------
extern "C" void kernel_launch(void* const* d_in, const int* in_sizes, int n_in,
                              void* d_out, int out_size) {
    const float* conv0 = (const float*)d_in[0];
    const float* conv1 = (const float*)d_in[1];
    const float* conv2 = (const float*)d_in[2];
    const float* conv3 = (const float*)d_in[3];
    const float* pos   = (const float*)d_in[4];
    const float* feat  = (const float*)d_in[5];
    const float* adj   = (const float*)d_in[6];
    const float* lin_w = (const float*)d_in[7];
    const float* lin_b = (const float*)d_in[8];
    const float* rw[3][6];
    for (int r = 0; r < 3; r++)
        for (int k = 0; k < 6; k++)
            rw[r][k] = (const float*)d_in[9 + r * 6 + k];
    const float* gf_w0 = (const float*)d_in[27];
    const float* gf_w1 = (const float*)d_in[28];
    float* out = (float*)d_out;

    float *skip, *t, *h2, *hfloat;
    cudaGetSymbolAddress((void**)&skip, g_skip);
    cudaGetSymbolAddress((void**)&t, g_t);
    cudaGetSymbolAddress((void**)&h2, g_h2);
    cudaGetSymbolAddress((void**)&hfloat, g_hf);
    __nv_bfloat16 *ahi, *alo, *hhi, *hlo, *ohi, *olo;
    cudaGetSymbolAddress((void**)&ahi, g_ahi);
    cudaGetSymbolAddress((void**)&alo, g_alo);
    cudaGetSymbolAddress((void**)&hhi, g_hhi);
    cudaGetSymbolAddress((void**)&hlo, g_hlo);
    cudaGetSymbolAddress((void**)&ohi, g_ohi);
    cudaGetSymbolAddress((void**)&olo, g_olo);

    cudaFuncSetAttribute(k_mmagemm, cudaFuncAttributeMaxDynamicSharedMemorySize, SM_TOTAL);

    static cudaStream_t s_side = nullptr;
    static cudaEvent_t e_fork = nullptr, e_join = nullptr;
    if (!s_side) {
        cudaStreamCreateWithFlags(&s_side, cudaStreamNonBlocking);
        cudaEventCreateWithFlags(&e_fork, cudaEventDisableTiming);
        cudaEventCreateWithFlags(&e_join, cudaEventDisableTiming);
    }

    WPrep wp;
    const int Ks3[3] = {259, 128, 128};
    for (int rb = 0; rb < 3; rb++) {
        int cin = Ks3[rb];
        wp.W[rb * 5 + 0] = rw[rb][0]; wp.K[rb * 5 + 0] = cin;
        wp.W[rb * 5 + 1] = rw[rb][2]; wp.K[rb * 5 + 1] = cin;
        wp.W[rb * 5 + 2] = rw[rb][3]; wp.K[rb * 5 + 2] = cin;
        wp.W[rb * 5 + 3] = rw[rb][4]; wp.K[rb * 5 + 3] = 128;
        wp.W[rb * 5 + 4] = rw[rb][5]; wp.K[rb * 5 + 4] = 128;
    }

    // fork: csr + wprep on the side stream
    cudaEventRecord(e_fork, 0);
    cudaStreamWaitEvent(s_side, e_fork, 0);
    k_csr<<<(BN * 32 + 255) / 256, 256, 0, s_side>>>(adj);
    k_wprep<<<dim3((128 * KPAD + 255) / 256, 15), 256, 0, s_side>>>(wp);
    cudaEventRecord(e_join, s_side);

    k_prep<<<(BN + 255) / 256, 256>>>(pos);   // resets g_slot, builds active list
    k_align_m<<<dim3((BN + 7) / 8, NSLAB), 256>>>(conv0, conv1, conv2, conv3, lin_w);
    k_split<<<(BN * KPAD + 255) / 256, 256>>>(lin_b, feat, pos);  // concat+align-reduce+split

    const int RB = (GM + 127) / 128;  // 78 row tiles
    const int CB = (BN + 7) / 8;      // 1233 combine blocks
    const __nv_bfloat16* Ahis[3] = {ahi, ohi, ohi};
    const __nv_bfloat16* Alos[3] = {alo, olo, olo};
    const int ldas[3] = {KPAD, 128, 128};
    const int nkbs[3] = {5, 2, 2};

    cudaStreamWaitEvent(0, e_join, 0);

    for (int rb = 0; rb < 3; rb++) {
        TcArgs a1;
        a1.wslab[0] = rb * 5 + 0; a1.bias[0] = rw[rb][1]; a1.Y[0] = skip;
        a1.wslab[1] = rb * 5 + 1; a1.bias[1] = nullptr;   a1.Y[1] = hfloat;
        a1.wslab[2] = rb * 5 + 2; a1.bias[2] = nullptr;   a1.Y[2] = t;
        k_mmagemm<<<dim3(RB, 3), 256, SM_TOTAL>>>(Ahis[rb], Alos[rb], ldas[rb], nkbs[rb], a1);
        k_combine<<<CB, 256>>>(hfloat, t, nullptr, hhi, hlo, nullptr, nullptr);

        TcArgs a2;
        a2.wslab[0] = rb * 5 + 3; a2.bias[0] = nullptr; a2.Y[0] = h2;
        a2.wslab[1] = rb * 5 + 4; a2.bias[1] = nullptr; a2.Y[1] = t;
        a2.wslab[2] = rb * 5 + 3; a2.bias[2] = nullptr; a2.Y[2] = h2;  // unused
        k_mmagemm<<<dim3(RB, 2), 256, SM_TOTAL>>>(hhi, hlo, 128, 2, a2);
        bool last = (rb == 2);
        k_combine<<<CB, 256>>>(h2, t, skip,
                               last ? nullptr : ohi, last ? nullptr : olo,
                               last ? gf_w0 : nullptr, last ? gf_w1 : nullptr);
    }

    k_final<<<(BN * 3 + 255) / 256, 256>>>(pos, out);
}

// round 15
// speedup vs baseline: 1.5309x; 1.0280x over previous
#include <cuda_runtime.h>
#include <cuda_bf16.h>
#include <math.h>
#include <stdint.h>
#include <string.h>

#define Bc 4
#define Nv 2466
#define BN (Bc * Nv)          // 9864
#define NBR_CAP 96
#define GM BN
#define KPAD 320              // 5 K-blocks of 64 (max K=259)
#define NSLAB 15              // align channel slabs of 256

// ---------------- scratch (device globals; no allocs) ----------------
__device__ float g_hf[BN * 128];   // float h scratch
__device__ float g_skip[BN * 128];
__device__ float g_t[BN * 128];
__device__ float g_h2[BN * 128];
__device__ float g_h3[BN * 3];
__device__ float g_t3[BN * 3];
__device__ int   g_nbr[BN * NBR_CAP];
__device__ int   g_ncnt[BN];
__device__ int   g_act_off[4 * BN];
__device__ float g_act_wg[4 * BN];
__device__ float g_apart[NSLAB * BN * 128];
__device__ int   g_act_cnt;
__device__ int   g_slot[BN];
__device__ __nv_bfloat16 g_wt_hi[15 * 128 * KPAD];  // W^T [slab][n][k]
__device__ __nv_bfloat16 g_wt_lo[15 * 128 * KPAD];
__device__ __nv_bfloat16 g_ahi[BN * KPAD];          // stage-0 X split (zero-padded)
__device__ __nv_bfloat16 g_alo[BN * KPAD];
__device__ __nv_bfloat16 g_hhi[BN * 128];           // mid-stage h split
__device__ __nv_bfloat16 g_hlo[BN * 128];
__device__ __nv_bfloat16 g_ohi[BN * 128];           // stage-output split
__device__ __nv_bfloat16 g_olo[BN * 128];

// ---------------- helpers ----------------
__device__ __forceinline__ uint32_t smem_u32(const void* p) {
    uint32_t a;
    asm("{ .reg .u64 t; cvta.to.shared.u64 t, %1; cvt.u32.u64 %0, t; }" : "=r"(a) : "l"(p));
    return a;
}

#define LDSM_X4(r0, r1, r2, r3, addr)                                            \
    asm volatile("ldmatrix.sync.aligned.m8n8.x4.shared.b16 {%0,%1,%2,%3}, [%4];" \
        : "=r"(r0), "=r"(r1), "=r"(r2), "=r"(r3) : "r"(addr))

#define CP_ASYNC16(dst, src, sz)                                                 \
    asm volatile("cp.async.cg.shared.global [%0], [%1], 16, %2;"                 \
        :: "r"(dst), "l"(src), "r"(sz))
#define CP_COMMIT() asm volatile("cp.async.commit_group;")
#define CP_WAIT0()  asm volatile("cp.async.wait_group 0;")

__device__ __forceinline__ void mma_bf16(float* d, const uint32_t* a,
                                         uint32_t b0, uint32_t b1) {
    asm volatile(
        "mma.sync.aligned.m16n8k16.row.col.f32.bf16.bf16.f32 "
        "{%0,%1,%2,%3}, {%4,%5,%6,%7}, {%8,%9}, {%0,%1,%2,%3};"
        : "+f"(d[0]), "+f"(d[1]), "+f"(d[2]), "+f"(d[3])
        : "r"(a[0]), "r"(a[1]), "r"(a[2]), "r"(a[3]), "r"(b0), "r"(b1));
}

// ---------------- vertex projection / active-list build (resets g_slot) ----------------
__global__ void k_prep(const float* __restrict__ pos) {
    int v = blockIdx.x * blockDim.x + threadIdx.x;
    if (v >= BN) return;
    g_slot[v] = -1;
    int b = v / Nv;
    float px = pos[v * 3 + 0], py = pos[v * 3 + 1], pz = pos[v * 3 + 2];
    float h = 248.f * (py / pz) + 111.5f;
    h = fminf(fmaxf(h, 0.f), 223.f);
    float w = 248.f * (px / (-pz)) + 111.5f;
    w = fminf(fmaxf(w, 0.f), 223.f);

    const int   Ss[4] = {56, 28, 14, 7};
    const int   Cs[4] = {256, 512, 1024, 2048};
    const float rs[4] = {0.25f, 0.125f, 0.0625f, 0.03125f};

    int off[4]; float wg[4]; bool any = false;
#pragma unroll
    for (int m = 0; m < 4; m++) {
        int S = Ss[m];
        float x = h * rs[m], y = w * rs[m];
        int x1 = (int)floorf(x);
        int x2 = min((int)ceilf(x), S - 1);
        int y1 = (int)floorf(y);
        int y2 = min((int)ceilf(y), S - 1);
        int wi = (x2 - x1) * (y2 - y1);
        off[m] = b * Cs[m] * S * S + x1 * S + y1;
        wg[m] = (float)wi;
        any = any || (wi != 0);
    }
    if (any) {
        int slot = atomicAdd(&g_act_cnt, 1);
        g_slot[v] = slot;
#pragma unroll
        for (int m = 0; m < 4; m++) {
            g_act_off[m * BN + slot] = off[m];
            g_act_wg[m * BN + slot]  = wg[m];
        }
    }
}

// ---------------- sparse align: 8 vertices/block, 15 slabs, float4 LDS inner loop ----------------
__global__ __launch_bounds__(256, 4)
void k_align_m(const float* __restrict__ f0, const float* __restrict__ f1,
               const float* __restrict__ f2, const float* __restrict__ f3,
               const float* __restrict__ lin_w) {
    int base = blockIdx.x * 8;
    int slab = blockIdx.y;
    int cnt = g_act_cnt;
    if (base >= cnt) return;

    // slab -> (feature map, channel offset within map)
    const int ms[NSLAB]    = {0, 1, 1, 2, 2, 2, 2, 3, 3, 3, 3, 3, 3, 3, 3};
    const int coffs[NSLAB] = {0, 0, 256, 0, 256, 512, 768,
                              0, 256, 512, 768, 1024, 1280, 1536, 1792};
    int m = ms[slab];
    int coff = coffs[slab];

    __shared__ float sval[2][8][32];
    __shared__ float sacc[8][128];
    __shared__ int   s_off[8];
    __shared__ float s_wg[8];

    int tid = threadIdx.x;
    int grp = tid >> 7;
    int j = tid & 127;
    if (tid < 8) {
        int i = base + tid;
        if (i < cnt) {
            s_off[tid] = g_act_off[m * BN + i];
            s_wg[tid]  = g_act_wg[m * BN + i];
        } else { s_off[tid] = 0; s_wg[tid] = 0.f; }
    }
    __syncthreads();

    const float* fs[4] = {f0, f1, f2, f3};
    const int SSs[4]    = {56 * 56, 28 * 28, 14 * 14, 7 * 7};
    const int cbase4[4] = {0, 256, 768, 1792};

    const float* f = fs[m];
    int SS = SSs[m];
    int cbase = cbase4[m] + coff;    // global channel base for lin_w row index
    int cend = coff + 256;

    int r0 = (tid & 127) >> 5;
    int cl = tid & 31;
    size_t o0 = (size_t)s_off[r0]     + (size_t)cl * SS;
    size_t o1 = (size_t)s_off[r0 + 4] + (size_t)cl * SS;
    float w0 = s_wg[r0], w1 = s_wg[r0 + 4];

    float acc[8] = {0.f, 0.f, 0.f, 0.f, 0.f, 0.f, 0.f, 0.f};
    int c0 = coff + grp * 32;
    float rg0 = w0 * __ldg(f + o0 + (size_t)c0 * SS);
    float rg1 = w1 * __ldg(f + o1 + (size_t)c0 * SS);

    for (; c0 < cend; c0 += 64) {
        sval[grp][r0][cl]     = rg0;
        sval[grp][r0 + 4][cl] = rg1;
        __syncthreads();
        int cn = c0 + 64;
        if (cn < cend) {
            rg0 = w0 * __ldg(f + o0 + (size_t)cn * SS);
            rg1 = w1 * __ldg(f + o1 + (size_t)cn * SS);
        }
        const float* wl = lin_w + (size_t)(cbase + (c0 - coff)) * 128 + j;
#pragma unroll
        for (int cc4 = 0; cc4 < 8; cc4++) {
            float4 sv[8];
#pragma unroll
            for (int r = 0; r < 8; r++)
                sv[r] = *(const float4*)&sval[grp][r][cc4 * 4];
            const float* wb = wl + (size_t)(cc4 * 4) * 128;
            float wv0 = wb[0], wv1 = wb[128], wv2 = wb[256], wv3 = wb[384];
#pragma unroll
            for (int r = 0; r < 8; r++) {
                acc[r] += sv[r].x * wv0;
                acc[r] += sv[r].y * wv1;
                acc[r] += sv[r].z * wv2;
                acc[r] += sv[r].w * wv3;
            }
        }
        __syncthreads();
    }
    if (grp == 1) {
#pragma unroll
        for (int r = 0; r < 8; r++) sacc[r][j] = acc[r];
    }
    __syncthreads();
    if (grp == 0) {
#pragma unroll
        for (int r = 0; r < 8; r++) {
            int i = base + r;
            if (i < cnt) g_apart[((size_t)slab * BN + i) * 128 + j] = acc[r] + sacc[r][j];
        }
    }
}

// ---------------- build stage-0 X split directly; reset g_act_cnt ----------------
__global__ void k_split(const float* __restrict__ lin_b,
                        const float* __restrict__ feat,
                        const float* __restrict__ pos) {
    int idx = blockIdx.x * blockDim.x + threadIdx.x;
    if (idx == 0) g_act_cnt = 0;   // reset for next replay (all readers precede this kernel)
    if (idx >= BN * KPAD) return;
    int v = idx / KPAD, c = idx % KPAD;
    float val = 0.f;
    if (c < 128) {
        val = lin_b[c];
        int s = g_slot[v];
        if (s >= 0) {
            float acc = 0.f;
#pragma unroll
            for (int sl = 0; sl < NSLAB; sl++)
                acc += g_apart[((size_t)sl * BN + s) * 128 + c];
            val += acc;
        }
    } else if (c < 256) {
        val = feat[v * 128 + (c - 128)];
    } else if (c < 259) {
        val = pos[v * 3 + (c - 256)];
    }
    __nv_bfloat16 hi = __float2bfloat16(val);
    g_ahi[idx] = hi;
    g_alo[idx] = __float2bfloat16(val - __bfloat162float(hi));
}

// ---------------- CSR build: warp/row, batched float2 + ballot compaction ----------------
__global__ void k_csr(const float* __restrict__ adj) {
    int warp = (blockIdx.x * blockDim.x + threadIdx.x) >> 5;
    if (warp >= BN) return;
    int lane = threadIdx.x & 31;
    int row = warp;
    int gb = (row / Nv) * Nv;
    const float* a = adj + (size_t)row * Nv;
    int* nb = &g_nbr[row * NBR_CAP];

    unsigned below = (1u << lane) - 1u;
    int base = 0;
    for (int it0 = 0; it0 < 40; it0 += 4) {
        float2 v[4];
#pragma unroll
        for (int u = 0; u < 4; u++) {
            int col = (it0 + u) * 64 + lane * 2;
            v[u] = make_float2(0.f, 0.f);
            if (col + 1 < Nv)      v[u] = *(const float2*)(a + col);
            else if (col < Nv)     v[u].x = a[col];
        }
#pragma unroll
        for (int u = 0; u < 4; u++) {
            int col = (it0 + u) * 64 + lane * 2;
            unsigned b0 = __ballot_sync(0xffffffffu, v[u].x != 0.f);
            unsigned b1 = __ballot_sync(0xffffffffu, v[u].y != 0.f);
            if (v[u].x != 0.f) {
                int p = base + __popc(b0 & below) + __popc(b1 & below);
                if (p < NBR_CAP) nb[p] = gb + col;
            }
            if (v[u].y != 0.f) {
                int p = base + __popc(b0 & (below | (1u << lane))) + __popc(b1 & below);
                if (p < NBR_CAP) nb[p] = gb + col + 1;
            }
            base += __popc(b0) + __popc(b1);
        }
    }
    if (lane == 0) g_ncnt[row] = min(base, NBR_CAP);
}

// ---------------- weight transpose + bf16 split ----------------
struct WPrep { const float* W[15]; int K[15]; };

__global__ void k_wprep(WPrep p) {
    int slab = blockIdx.y;
    int idx = blockIdx.x * blockDim.x + threadIdx.x;
    if (idx >= 128 * KPAD) return;
    int n = idx / KPAD, k = idx % KPAD;
    int K = p.K[slab];
    float w = (k < K) ? p.W[slab][(size_t)k * 128 + n] : 0.f;
    __nv_bfloat16 hi = __float2bfloat16(w);
    float lo = w - __bfloat162float(hi);
    g_wt_hi[(size_t)slab * 128 * KPAD + idx] = hi;
    g_wt_lo[(size_t)slab * 128 * KPAD + idx] = __float2bfloat16(lo);
}

// ---------------- mma.sync bf16-split GEMM (pre-split A, cp.async, swizzled) ----------------
struct TcArgs {
    int          wslab[3];
    const float* bias[3];
    float*       Y[3];
};

#define SA_HI 0
#define SA_LO 16384
#define SB_HI 32768
#define SB_LO 49152
#define SM_TOTAL 65536

__global__ __launch_bounds__(256, 2)
void k_mmagemm(const __nv_bfloat16* __restrict__ Ahi,
               const __nv_bfloat16* __restrict__ Alo,
               int lda, int nkb, TcArgs args) {
    extern __shared__ char smem[];
    uint32_t sb = smem_u32(smem);
    int tid = threadIdx.x;
    int lane = tid & 31;
    int w = tid >> 5;
    int slab = blockIdx.y;
    int row0 = blockIdx.x * 128;

    const __nv_bfloat16* Wh = g_wt_hi + (size_t)args.wslab[slab] * 128 * KPAD;
    const __nv_bfloat16* Wl = g_wt_lo + (size_t)args.wslab[slab] * 128 * KPAD;

    int mrow0 = (w >> 1) * 32;
    int ncol0 = (w & 1) * 64;

    int a_row = mrow0 + (lane & 7) + (lane & 8);
    uint32_t a_base = sb + (uint32_t)(a_row * 128);
    int a_sel = (lane >> 4) & 1;
    int a_r7 = a_row & 7;

    int b_n = ncol0 + (lane & 7) + ((lane & 16) ? 8 : 0);
    uint32_t b_base = sb + (uint32_t)(b_n * 128);
    int b_sel = (lane >> 3) & 1;
    int b_r7 = b_n & 7;

    int cr[4], cc[4];
    uint32_t cdst[4];
#pragma unroll
    for (int i = 0; i < 4; i++) {
        int e = tid + i * 256;
        cr[i] = e >> 3;
        cc[i] = e & 7;
        cdst[i] = (uint32_t)(cr[i] * 128 + ((cc[i] ^ (cr[i] & 7)) << 4));
    }

    float acc[2][8][4];
#pragma unroll
    for (int mt = 0; mt < 2; mt++)
#pragma unroll
        for (int nt = 0; nt < 8; nt++)
#pragma unroll
            for (int q = 0; q < 4; q++) acc[mt][nt][q] = 0.f;

    for (int kb = 0; kb < nkb; kb++) {
        int k0 = kb * 64;
#pragma unroll
        for (int i = 0; i < 4; i++) {
            int gr = row0 + cr[i];
            int ok = (gr < GM);
            size_t srcoff = (size_t)(ok ? gr : 0) * lda + k0 + cc[i] * 8;
            uint32_t sz = ok ? 16u : 0u;
            CP_ASYNC16(sb + SA_HI + cdst[i], Ahi + srcoff, sz);
            CP_ASYNC16(sb + SA_LO + cdst[i], Alo + srcoff, sz);
        }
#pragma unroll
        for (int i = 0; i < 4; i++) {
            size_t srcoff = (size_t)cr[i] * KPAD + k0 + cc[i] * 8;
            CP_ASYNC16(sb + SB_HI + cdst[i], Wh + srcoff, 16u);
            CP_ASYNC16(sb + SB_LO + cdst[i], Wl + srcoff, 16u);
        }
        CP_COMMIT();
        CP_WAIT0();
        __syncthreads();

#pragma unroll
        for (int ks = 0; ks < 4; ks++) {
            uint32_t aco = (uint32_t)(((2 * ks + a_sel) ^ a_r7) << 4);
            uint32_t ah[2][4], al[2][4];
#pragma unroll
            for (int mt = 0; mt < 2; mt++) {
                uint32_t ao = (uint32_t)(mt * 2048) + aco;
                LDSM_X4(ah[mt][0], ah[mt][1], ah[mt][2], ah[mt][3], a_base + SA_HI + ao);
                LDSM_X4(al[mt][0], al[mt][1], al[mt][2], al[mt][3], a_base + SA_LO + ao);
            }
            uint32_t bco = (uint32_t)(((2 * ks + b_sel) ^ b_r7) << 4);
#pragma unroll
            for (int nt2 = 0; nt2 < 4; nt2++) {
                uint32_t bo = (uint32_t)(nt2 * 2048) + bco;
                uint32_t bh0, bh1, bh2, bh3, bl0, bl1, bl2, bl3;
                LDSM_X4(bh0, bh1, bh2, bh3, b_base + SB_HI + bo);
                LDSM_X4(bl0, bl1, bl2, bl3, b_base + SB_LO + bo);
#pragma unroll
                for (int mt = 0; mt < 2; mt++) {
                    mma_bf16(acc[mt][nt2 * 2],     ah[mt], bh0, bh1);
                    mma_bf16(acc[mt][nt2 * 2],     ah[mt], bl0, bl1);
                    mma_bf16(acc[mt][nt2 * 2],     al[mt], bh0, bh1);
                    mma_bf16(acc[mt][nt2 * 2 + 1], ah[mt], bh2, bh3);
                    mma_bf16(acc[mt][nt2 * 2 + 1], ah[mt], bl2, bl3);
                    mma_bf16(acc[mt][nt2 * 2 + 1], al[mt], bh2, bh3);
                }
            }
        }
        __syncthreads();
    }

    const float* bias = args.bias[slab];
    float* Y = args.Y[slab];
    int group = lane >> 2, tig = lane & 3;
#pragma unroll
    for (int mt = 0; mt < 2; mt++) {
        int r1 = row0 + mrow0 + mt * 16 + group;
        int r2 = r1 + 8;
#pragma unroll
        for (int nt = 0; nt < 8; nt++) {
            int c = ncol0 + nt * 8 + tig * 2;
            float b0 = bias ? bias[c] : 0.f;
            float b1 = bias ? bias[c + 1] : 0.f;
            if (r1 < GM) {
                Y[(size_t)r1 * 128 + c]     = acc[mt][nt][0] + b0;
                Y[(size_t)r1 * 128 + c + 1] = acc[mt][nt][1] + b1;
            }
            if (r2 < GM) {
                Y[(size_t)r2 * 128 + c]     = acc[mt][nt][2] + b0;
                Y[(size_t)r2 * 128 + c + 1] = acc[mt][nt][3] + b1;
            }
        }
    }
}

// ---------------- SpMM + relu (+skip); MLP-batched gathers; bf16 split / fused gemm3 ----------------
__global__ void k_combine(const float* __restrict__ H, const float* __restrict__ T,
                          const float* __restrict__ S,
                          __nv_bfloat16* __restrict__ Ohi, __nv_bfloat16* __restrict__ Olo,
                          const float* __restrict__ W0, const float* __restrict__ W1) {
    int row = blockIdx.x * 8 + (threadIdx.x >> 5);
    if (row >= BN) return;
    int lane = threadIdx.x & 31;
    int cnt = g_ncnt[row];
    const int* nb = &g_nbr[row * NBR_CAP];
    size_t o = (size_t)row * 128 + lane * 4;
    float4 a = *(const float4*)&H[o];
    int k = 0;
    for (; k + 4 <= cnt; k += 4) {   // 4 independent gathers in flight
        int n0 = nb[k], n1 = nb[k + 1], n2 = nb[k + 2], n3 = nb[k + 3];
        float4 v0 = *(const float4*)&T[(size_t)n0 * 128 + lane * 4];
        float4 v1 = *(const float4*)&T[(size_t)n1 * 128 + lane * 4];
        float4 v2 = *(const float4*)&T[(size_t)n2 * 128 + lane * 4];
        float4 v3 = *(const float4*)&T[(size_t)n3 * 128 + lane * 4];
        a.x += (v0.x + v1.x) + (v2.x + v3.x);
        a.y += (v0.y + v1.y) + (v2.y + v3.y);
        a.z += (v0.z + v1.z) + (v2.z + v3.z);
        a.w += (v0.w + v1.w) + (v2.w + v3.w);
    }
    for (; k < cnt; k++) {
        const float4 v = *(const float4*)&T[(size_t)nb[k] * 128 + lane * 4];
        a.x += v.x; a.y += v.y; a.z += v.z; a.w += v.w;
    }
    a.x = fmaxf(a.x, 0.f); a.y = fmaxf(a.y, 0.f);
    a.z = fmaxf(a.z, 0.f); a.w = fmaxf(a.w, 0.f);
    if (S) {
        const float4 s = *(const float4*)&S[o];
        a.x += s.x; a.y += s.y; a.z += s.z; a.w += s.w;
    }
    float vv[4] = {a.x, a.y, a.z, a.w};
    if (Ohi) {
        __nv_bfloat16 h[4], l[4];
#pragma unroll
        for (int q = 0; q < 4; q++) {
            h[q] = __float2bfloat16(vv[q]);
            l[q] = __float2bfloat16(vv[q] - __bfloat162float(h[q]));
        }
        uint2 hp, lp;
        memcpy(&hp, h, 8);
        memcpy(&lp, l, 8);
        *(uint2*)&Ohi[o] = hp;
        *(uint2*)&Olo[o] = lp;
    }
    if (W0) {  // fused final 128->3 double GEMM (warp-level reduction)
        float s6[6] = {0.f, 0.f, 0.f, 0.f, 0.f, 0.f};
#pragma unroll
        for (int q = 0; q < 4; q++) {
            int kk = lane * 4 + q;
#pragma unroll
            for (int j = 0; j < 3; j++) {
                s6[j]     += vv[q] * W0[kk * 3 + j];
                s6[3 + j] += vv[q] * W1[kk * 3 + j];
            }
        }
#pragma unroll
        for (int off = 16; off > 0; off >>= 1)
#pragma unroll
            for (int i = 0; i < 6; i++)
                s6[i] += __shfl_xor_sync(0xffffffffu, s6[i], off);
        if (lane == 0) {
#pragma unroll
            for (int j = 0; j < 3; j++) {
                g_h3[row * 3 + j] = s6[j];
                g_t3[row * 3 + j] = s6[3 + j];
            }
        }
    }
}

// ---------------- final spmm + tanh(relu) + positions ----------------
__global__ void k_final(const float* __restrict__ pos, float* __restrict__ out) {
    int idx = blockIdx.x * blockDim.x + threadIdx.x;
    if (idx >= BN * 3) return;
    int row = idx / 3, j = idx % 3;
    int cnt = g_ncnt[row];
    const int* nb = &g_nbr[row * NBR_CAP];
    float acc = g_h3[idx];
    for (int k = 0; k < cnt; k++) acc += g_t3[(size_t)nb[k] * 3 + j];
    out[idx] = pos[idx] + tanhf(fmaxf(acc, 0.f));
}

// ---------------- launch ----------------
extern "C" void kernel_launch(void* const* d_in, const int* in_sizes, int n_in,
                              void* d_out, int out_size) {
    const float* conv0 = (const float*)d_in[0];
    const float* conv1 = (const float*)d_in[1];
    const float* conv2 = (const float*)d_in[2];
    const float* conv3 = (const float*)d_in[3];
    const float* pos   = (const float*)d_in[4];
    const float* feat  = (const float*)d_in[5];
    const float* adj   = (const float*)d_in[6];
    const float* lin_w = (const float*)d_in[7];
    const float* lin_b = (const float*)d_in[8];
    const float* rw[3][6];
    for (int r = 0; r < 3; r++)
        for (int k = 0; k < 6; k++)
            rw[r][k] = (const float*)d_in[9 + r * 6 + k];
    const float* gf_w0 = (const float*)d_in[27];
    const float* gf_w1 = (const float*)d_in[28];
    float* out = (float*)d_out;

    float *skip, *t, *h2, *hfloat;
    cudaGetSymbolAddress((void**)&skip, g_skip);
    cudaGetSymbolAddress((void**)&t, g_t);
    cudaGetSymbolAddress((void**)&h2, g_h2);
    cudaGetSymbolAddress((void**)&hfloat, g_hf);
    __nv_bfloat16 *ahi, *alo, *hhi, *hlo, *ohi, *olo;
    cudaGetSymbolAddress((void**)&ahi, g_ahi);
    cudaGetSymbolAddress((void**)&alo, g_alo);
    cudaGetSymbolAddress((void**)&hhi, g_hhi);
    cudaGetSymbolAddress((void**)&hlo, g_hlo);
    cudaGetSymbolAddress((void**)&ohi, g_ohi);
    cudaGetSymbolAddress((void**)&olo, g_olo);

    cudaFuncSetAttribute(k_mmagemm, cudaFuncAttributeMaxDynamicSharedMemorySize, SM_TOTAL);

    static cudaStream_t s_side = nullptr;
    static cudaEvent_t e_fork = nullptr, e_join = nullptr;
    if (!s_side) {
        cudaStreamCreateWithFlags(&s_side, cudaStreamNonBlocking);
        cudaEventCreateWithFlags(&e_fork, cudaEventDisableTiming);
        cudaEventCreateWithFlags(&e_join, cudaEventDisableTiming);
    }

    WPrep wp;
    const int Ks3[3] = {259, 128, 128};
    for (int rb = 0; rb < 3; rb++) {
        int cin = Ks3[rb];
        wp.W[rb * 5 + 0] = rw[rb][0]; wp.K[rb * 5 + 0] = cin;
        wp.W[rb * 5 + 1] = rw[rb][2]; wp.K[rb * 5 + 1] = cin;
        wp.W[rb * 5 + 2] = rw[rb][3]; wp.K[rb * 5 + 2] = cin;
        wp.W[rb * 5 + 3] = rw[rb][4]; wp.K[rb * 5 + 3] = 128;
        wp.W[rb * 5 + 4] = rw[rb][5]; wp.K[rb * 5 + 4] = 128;
    }

    // fork: csr + wprep on the side stream
    cudaEventRecord(e_fork, 0);
    cudaStreamWaitEvent(s_side, e_fork, 0);
    k_csr<<<(BN * 32 + 255) / 256, 256, 0, s_side>>>(adj);
    k_wprep<<<dim3((128 * KPAD + 255) / 256, 15), 256, 0, s_side>>>(wp);
    cudaEventRecord(e_join, s_side);

    k_prep<<<(BN + 255) / 256, 256>>>(pos);   // resets g_slot, builds active list
    k_align_m<<<dim3((BN + 7) / 8, NSLAB), 256>>>(conv0, conv1, conv2, conv3, lin_w);
    k_split<<<(BN * KPAD + 255) / 256, 256>>>(lin_b, feat, pos);  // concat+align-reduce+split

    const int RB = (GM + 127) / 128;  // 78 row tiles
    const int CB = (BN + 7) / 8;      // 1233 combine blocks
    const __nv_bfloat16* Ahis[3] = {ahi, ohi, ohi};
    const __nv_bfloat16* Alos[3] = {alo, olo, olo};
    const int ldas[3] = {KPAD, 128, 128};
    const int nkbs[3] = {5, 2, 2};

    cudaStreamWaitEvent(0, e_join, 0);

    for (int rb = 0; rb < 3; rb++) {
        TcArgs a1;
        a1.wslab[0] = rb * 5 + 0; a1.bias[0] = rw[rb][1]; a1.Y[0] = skip;
        a1.wslab[1] = rb * 5 + 1; a1.bias[1] = nullptr;   a1.Y[1] = hfloat;
        a1.wslab[2] = rb * 5 + 2; a1.bias[2] = nullptr;   a1.Y[2] = t;
        k_mmagemm<<<dim3(RB, 3), 256, SM_TOTAL>>>(Ahis[rb], Alos[rb], ldas[rb], nkbs[rb], a1);
        k_combine<<<CB, 256>>>(hfloat, t, nullptr, hhi, hlo, nullptr, nullptr);

        TcArgs a2;
        a2.wslab[0] = rb * 5 + 3; a2.bias[0] = nullptr; a2.Y[0] = h2;
        a2.wslab[1] = rb * 5 + 4; a2.bias[1] = nullptr; a2.Y[1] = t;
        a2.wslab[2] = rb * 5 + 3; a2.bias[2] = nullptr; a2.Y[2] = h2;  // unused
        k_mmagemm<<<dim3(RB, 2), 256, SM_TOTAL>>>(hhi, hlo, 128, 2, a2);
        bool last = (rb == 2);
        k_combine<<<CB, 256>>>(h2, t, skip,
                               last ? nullptr : ohi, last ? nullptr : olo,
                               last ? gf_w0 : nullptr, last ? gf_w1 : nullptr);
    }

    k_final<<<(BN * 3 + 255) / 256, 256>>>(pos, out);
}

// round 16
// speedup vs baseline: 1.6762x; 1.0950x over previous
#include <cuda_runtime.h>
#include <cuda_bf16.h>
#include <math.h>
#include <stdint.h>
#include <string.h>

#define Bc 4
#define Nv 2466
#define BN (Bc * Nv)          // 9864
#define NBR_CAP 96
#define GM BN
#define KPAD 320              // 5 K-blocks of 64 (max K=259)
#define NSLAB 15              // align K slabs of 256
#define KF 3840               // aligned-feature K

// ---------------- scratch (device globals; no allocs) ----------------
__device__ float g_hf[BN * 128];   // float h scratch
__device__ float g_skip[BN * 128];
__device__ float g_t[BN * 128];
__device__ float g_h2[BN * 128];
__device__ float g_h3[BN * 3];
__device__ float g_t3[BN * 3];
__device__ int   g_nbr[BN * NBR_CAP];
__device__ int   g_ncnt[BN];
__device__ int   g_act_off[4 * BN];
__device__ float g_act_wg[4 * BN];
__device__ float g_apart[NSLAB * BN * 128];
__device__ int   g_act_cnt;
__device__ int   g_slot[BN];
__device__ __nv_bfloat16 g_wt_hi[15 * 128 * KPAD];  // W^T [slab][n][k]
__device__ __nv_bfloat16 g_wt_lo[15 * 128 * KPAD];
__device__ __nv_bfloat16 g_lw_hi[128 * KF];         // lin_w^T [n][k]
__device__ __nv_bfloat16 g_lw_lo[128 * KF];
__device__ __nv_bfloat16 g_fhi[(size_t)BN * KF];    // gathered active features (zero-init)
__device__ __nv_bfloat16 g_flo[(size_t)BN * KF];
__device__ __nv_bfloat16 g_ahi[BN * KPAD];          // stage-0 X split (zero-padded)
__device__ __nv_bfloat16 g_alo[BN * KPAD];
__device__ __nv_bfloat16 g_hhi[BN * 128];           // mid-stage h split
__device__ __nv_bfloat16 g_hlo[BN * 128];
__device__ __nv_bfloat16 g_ohi[BN * 128];           // stage-output split
__device__ __nv_bfloat16 g_olo[BN * 128];

// ---------------- helpers ----------------
__device__ __forceinline__ uint32_t smem_u32(const void* p) {
    uint32_t a;
    asm("{ .reg .u64 t; cvta.to.shared.u64 t, %1; cvt.u32.u64 %0, t; }" : "=r"(a) : "l"(p));
    return a;
}

#define LDSM_X4(r0, r1, r2, r3, addr)                                            \
    asm volatile("ldmatrix.sync.aligned.m8n8.x4.shared.b16 {%0,%1,%2,%3}, [%4];" \
        : "=r"(r0), "=r"(r1), "=r"(r2), "=r"(r3) : "r"(addr))

#define CP_ASYNC16(dst, src, sz)                                                 \
    asm volatile("cp.async.cg.shared.global [%0], [%1], 16, %2;"                 \
        :: "r"(dst), "l"(src), "r"(sz))
#define CP_COMMIT() asm volatile("cp.async.commit_group;")
#define CP_WAIT0()  asm volatile("cp.async.wait_group 0;")

__device__ __forceinline__ void mma_bf16(float* d, const uint32_t* a,
                                         uint32_t b0, uint32_t b1) {
    asm volatile(
        "mma.sync.aligned.m16n8k16.row.col.f32.bf16.bf16.f32 "
        "{%0,%1,%2,%3}, {%4,%5,%6,%7}, {%8,%9}, {%0,%1,%2,%3};"
        : "+f"(d[0]), "+f"(d[1]), "+f"(d[2]), "+f"(d[3])
        : "r"(a[0]), "r"(a[1]), "r"(a[2]), "r"(a[3]), "r"(b0), "r"(b1));
}

// ---------------- vertex projection / active-list build (resets g_slot) ----------------
__global__ void k_prep(const float* __restrict__ pos) {
    int v = blockIdx.x * blockDim.x + threadIdx.x;
    if (v >= BN) return;
    g_slot[v] = -1;
    int b = v / Nv;
    float px = pos[v * 3 + 0], py = pos[v * 3 + 1], pz = pos[v * 3 + 2];
    float h = 248.f * (py / pz) + 111.5f;
    h = fminf(fmaxf(h, 0.f), 223.f);
    float w = 248.f * (px / (-pz)) + 111.5f;
    w = fminf(fmaxf(w, 0.f), 223.f);

    const int   Ss[4] = {56, 28, 14, 7};
    const int   Cs[4] = {256, 512, 1024, 2048};
    const float rs[4] = {0.25f, 0.125f, 0.0625f, 0.03125f};

    int off[4]; float wg[4]; bool any = false;
#pragma unroll
    for (int m = 0; m < 4; m++) {
        int S = Ss[m];
        float x = h * rs[m], y = w * rs[m];
        int x1 = (int)floorf(x);
        int x2 = min((int)ceilf(x), S - 1);
        int y1 = (int)floorf(y);
        int y2 = min((int)ceilf(y), S - 1);
        int wi = (x2 - x1) * (y2 - y1);
        off[m] = b * Cs[m] * S * S + x1 * S + y1;
        wg[m] = (float)wi;
        any = any || (wi != 0);
    }
    if (any) {
        int slot = atomicAdd(&g_act_cnt, 1);
        g_slot[v] = slot;
#pragma unroll
        for (int m = 0; m < 4; m++) {
            g_act_off[m * BN + slot] = off[m];
            g_act_wg[m * BN + slot]  = wg[m];
        }
    }
}

// ---------------- gather active-vertex weighted features, bf16 split ----------------
__global__ void k_gather(const float* __restrict__ f0, const float* __restrict__ f1,
                         const float* __restrict__ f2, const float* __restrict__ f3) {
    int i = blockIdx.x;
    if (i >= g_act_cnt) return;
    int tid = threadIdx.x;  // 256

    __shared__ int   soff[4];
    __shared__ float swg[4];
    if (tid < 4) {
        soff[tid] = g_act_off[tid * BN + i];
        swg[tid]  = g_act_wg[tid * BN + i];
    }
    __syncthreads();

    size_t rowb = (size_t)i * KF;
#pragma unroll
    for (int it = 0; it < KF / 256; it++) {
        int c = it * 256 + tid;
        const float* f; int cb, SS, m;
        if (c < 256)       { m = 0; cb = 0;    SS = 3136; f = f0; }
        else if (c < 768)  { m = 1; cb = 256;  SS = 784;  f = f1; }
        else if (c < 1792) { m = 2; cb = 768;  SS = 196;  f = f2; }
        else               { m = 3; cb = 1792; SS = 49;   f = f3; }
        float v = swg[m] * __ldg(f + (size_t)soff[m] + (size_t)(c - cb) * SS);
        __nv_bfloat16 hi = __float2bfloat16(v);
        g_fhi[rowb + c] = hi;
        g_flo[rowb + c] = __float2bfloat16(v - __bfloat162float(hi));
    }
}

// ---------------- lin_w transpose + bf16 split ----------------
__global__ void k_lwprep(const float* __restrict__ lin_w) {
    int idx = blockIdx.x * blockDim.x + threadIdx.x;
    if (idx >= 128 * KF) return;
    int n = idx / KF, k = idx % KF;
    float w = lin_w[(size_t)k * 128 + n];
    __nv_bfloat16 hi = __float2bfloat16(w);
    g_lw_hi[idx] = hi;
    g_lw_lo[idx] = __float2bfloat16(w - __bfloat162float(hi));
}

// ---------------- build stage-0 X split directly; reset g_act_cnt ----------------
__global__ void k_split(const float* __restrict__ lin_b,
                        const float* __restrict__ feat,
                        const float* __restrict__ pos) {
    int idx = blockIdx.x * blockDim.x + threadIdx.x;
    if (idx == 0) g_act_cnt = 0;   // reset for next replay (all readers precede this kernel)
    if (idx >= BN * KPAD) return;
    int v = idx / KPAD, c = idx % KPAD;
    float val = 0.f;
    if (c < 128) {
        val = lin_b[c];
        int s = g_slot[v];
        if (s >= 0) {
            float acc = 0.f;
#pragma unroll
            for (int sl = 0; sl < NSLAB; sl++)
                acc += g_apart[((size_t)sl * BN + s) * 128 + c];
            val += acc;
        }
    } else if (c < 256) {
        val = feat[v * 128 + (c - 128)];
    } else if (c < 259) {
        val = pos[v * 3 + (c - 256)];
    }
    __nv_bfloat16 hi = __float2bfloat16(val);
    g_ahi[idx] = hi;
    g_alo[idx] = __float2bfloat16(val - __bfloat162float(hi));
}

// ---------------- CSR build: warp/row, batched float2 + ballot compaction ----------------
__global__ void k_csr(const float* __restrict__ adj) {
    int warp = (blockIdx.x * blockDim.x + threadIdx.x) >> 5;
    if (warp >= BN) return;
    int lane = threadIdx.x & 31;
    int row = warp;
    int gb = (row / Nv) * Nv;
    const float* a = adj + (size_t)row * Nv;
    int* nb = &g_nbr[row * NBR_CAP];

    unsigned below = (1u << lane) - 1u;
    int base = 0;
    for (int it0 = 0; it0 < 40; it0 += 4) {
        float2 v[4];
#pragma unroll
        for (int u = 0; u < 4; u++) {
            int col = (it0 + u) * 64 + lane * 2;
            v[u] = make_float2(0.f, 0.f);
            if (col + 1 < Nv)      v[u] = *(const float2*)(a + col);
            else if (col < Nv)     v[u].x = a[col];
        }
#pragma unroll
        for (int u = 0; u < 4; u++) {
            int col = (it0 + u) * 64 + lane * 2;
            unsigned b0 = __ballot_sync(0xffffffffu, v[u].x != 0.f);
            unsigned b1 = __ballot_sync(0xffffffffu, v[u].y != 0.f);
            if (v[u].x != 0.f) {
                int p = base + __popc(b0 & below) + __popc(b1 & below);
                if (p < NBR_CAP) nb[p] = gb + col;
            }
            if (v[u].y != 0.f) {
                int p = base + __popc(b0 & (below | (1u << lane))) + __popc(b1 & below);
                if (p < NBR_CAP) nb[p] = gb + col + 1;
            }
            base += __popc(b0) + __popc(b1);
        }
    }
    if (lane == 0) g_ncnt[row] = min(base, NBR_CAP);
}

// ---------------- weight transpose + bf16 split ----------------
struct WPrep { const float* W[15]; int K[15]; };

__global__ void k_wprep(WPrep p) {
    int slab = blockIdx.y;
    int idx = blockIdx.x * blockDim.x + threadIdx.x;
    if (idx >= 128 * KPAD) return;
    int n = idx / KPAD, k = idx % KPAD;
    int K = p.K[slab];
    float w = (k < K) ? p.W[slab][(size_t)k * 128 + n] : 0.f;
    __nv_bfloat16 hi = __float2bfloat16(w);
    float lo = w - __bfloat162float(hi);
    g_wt_hi[(size_t)slab * 128 * KPAD + idx] = hi;
    g_wt_lo[(size_t)slab * 128 * KPAD + idx] = __float2bfloat16(lo);
}

// ---------------- mma.sync bf16-split GEMM (pre-split A, cp.async, swizzled) ----------------
struct TcArgs {
    int          wslab[3];
    const float* bias[3];
    float*       Y[3];
};

#define SA_HI 0
#define SA_LO 16384
#define SB_HI 32768
#define SB_LO 49152
#define SM_TOTAL 65536

__global__ __launch_bounds__(256, 2)
void k_mmagemm(const __nv_bfloat16* __restrict__ Ahi,
               const __nv_bfloat16* __restrict__ Alo,
               int lda, int nkb, TcArgs args) {
    extern __shared__ char smem[];
    uint32_t sb = smem_u32(smem);
    int tid = threadIdx.x;
    int lane = tid & 31;
    int w = tid >> 5;
    int slab = blockIdx.y;
    int row0 = blockIdx.x * 128;

    const __nv_bfloat16* Wh = g_wt_hi + (size_t)args.wslab[slab] * 128 * KPAD;
    const __nv_bfloat16* Wl = g_wt_lo + (size_t)args.wslab[slab] * 128 * KPAD;

    int mrow0 = (w >> 1) * 32;
    int ncol0 = (w & 1) * 64;

    int a_row = mrow0 + (lane & 7) + (lane & 8);
    uint32_t a_base = sb + (uint32_t)(a_row * 128);
    int a_sel = (lane >> 4) & 1;
    int a_r7 = a_row & 7;

    int b_n = ncol0 + (lane & 7) + ((lane & 16) ? 8 : 0);
    uint32_t b_base = sb + (uint32_t)(b_n * 128);
    int b_sel = (lane >> 3) & 1;
    int b_r7 = b_n & 7;

    int cr[4], cc[4];
    uint32_t cdst[4];
#pragma unroll
    for (int i = 0; i < 4; i++) {
        int e = tid + i * 256;
        cr[i] = e >> 3;
        cc[i] = e & 7;
        cdst[i] = (uint32_t)(cr[i] * 128 + ((cc[i] ^ (cr[i] & 7)) << 4));
    }

    float acc[2][8][4];
#pragma unroll
    for (int mt = 0; mt < 2; mt++)
#pragma unroll
        for (int nt = 0; nt < 8; nt++)
#pragma unroll
            for (int q = 0; q < 4; q++) acc[mt][nt][q] = 0.f;

    for (int kb = 0; kb < nkb; kb++) {
        int k0 = kb * 64;
#pragma unroll
        for (int i = 0; i < 4; i++) {
            int gr = row0 + cr[i];
            int ok = (gr < GM);
            size_t srcoff = (size_t)(ok ? gr : 0) * lda + k0 + cc[i] * 8;
            uint32_t sz = ok ? 16u : 0u;
            CP_ASYNC16(sb + SA_HI + cdst[i], Ahi + srcoff, sz);
            CP_ASYNC16(sb + SA_LO + cdst[i], Alo + srcoff, sz);
        }
#pragma unroll
        for (int i = 0; i < 4; i++) {
            size_t srcoff = (size_t)cr[i] * KPAD + k0 + cc[i] * 8;
            CP_ASYNC16(sb + SB_HI + cdst[i], Wh + srcoff, 16u);
            CP_ASYNC16(sb + SB_LO + cdst[i], Wl + srcoff, 16u);
        }
        CP_COMMIT();
        CP_WAIT0();
        __syncthreads();

#pragma unroll
        for (int ks = 0; ks < 4; ks++) {
            uint32_t aco = (uint32_t)(((2 * ks + a_sel) ^ a_r7) << 4);
            uint32_t ah[2][4], al[2][4];
#pragma unroll
            for (int mt = 0; mt < 2; mt++) {
                uint32_t ao = (uint32_t)(mt * 2048) + aco;
                LDSM_X4(ah[mt][0], ah[mt][1], ah[mt][2], ah[mt][3], a_base + SA_HI + ao);
                LDSM_X4(al[mt][0], al[mt][1], al[mt][2], al[mt][3], a_base + SA_LO + ao);
            }
            uint32_t bco = (uint32_t)(((2 * ks + b_sel) ^ b_r7) << 4);
#pragma unroll
            for (int nt2 = 0; nt2 < 4; nt2++) {
                uint32_t bo = (uint32_t)(nt2 * 2048) + bco;
                uint32_t bh0, bh1, bh2, bh3, bl0, bl1, bl2, bl3;
                LDSM_X4(bh0, bh1, bh2, bh3, b_base + SB_HI + bo);
                LDSM_X4(bl0, bl1, bl2, bl3, b_base + SB_LO + bo);
#pragma unroll
                for (int mt = 0; mt < 2; mt++) {
                    mma_bf16(acc[mt][nt2 * 2],     ah[mt], bh0, bh1);
                    mma_bf16(acc[mt][nt2 * 2],     ah[mt], bl0, bl1);
                    mma_bf16(acc[mt][nt2 * 2],     al[mt], bh0, bh1);
                    mma_bf16(acc[mt][nt2 * 2 + 1], ah[mt], bh2, bh3);
                    mma_bf16(acc[mt][nt2 * 2 + 1], ah[mt], bl2, bl3);
                    mma_bf16(acc[mt][nt2 * 2 + 1], al[mt], bh2, bh3);
                }
            }
        }
        __syncthreads();
    }

    const float* bias = args.bias[slab];
    float* Y = args.Y[slab];
    int group = lane >> 2, tig = lane & 3;
#pragma unroll
    for (int mt = 0; mt < 2; mt++) {
        int r1 = row0 + mrow0 + mt * 16 + group;
        int r2 = r1 + 8;
#pragma unroll
        for (int nt = 0; nt < 8; nt++) {
            int c = ncol0 + nt * 8 + tig * 2;
            float b0 = bias ? bias[c] : 0.f;
            float b1 = bias ? bias[c + 1] : 0.f;
            if (r1 < GM) {
                Y[(size_t)r1 * 128 + c]     = acc[mt][nt][0] + b0;
                Y[(size_t)r1 * 128 + c + 1] = acc[mt][nt][1] + b1;
            }
            if (r2 < GM) {
                Y[(size_t)r2 * 128 + c]     = acc[mt][nt][2] + b0;
                Y[(size_t)r2 * 128 + c + 1] = acc[mt][nt][3] + b1;
            }
        }
    }
}

// ---------------- align GEMM: K-slab per blockIdx.y, dynamic M, A/B from gathered/lin_w ----------------
__global__ __launch_bounds__(256, 2)
void k_agemm() {
    int row0 = blockIdx.x * 128;
    if (row0 >= g_act_cnt) return;

    extern __shared__ char smem[];
    uint32_t sb = smem_u32(smem);
    int tid = threadIdx.x;
    int lane = tid & 31;
    int w = tid >> 5;
    int slab = blockIdx.y;           // K slab: [slab*256, slab*256+256)
    int koff = slab * 256;

    const __nv_bfloat16* Ahi = g_fhi;
    const __nv_bfloat16* Alo = g_flo;

    int mrow0 = (w >> 1) * 32;
    int ncol0 = (w & 1) * 64;

    int a_row = mrow0 + (lane & 7) + (lane & 8);
    uint32_t a_base = sb + (uint32_t)(a_row * 128);
    int a_sel = (lane >> 4) & 1;
    int a_r7 = a_row & 7;

    int b_n = ncol0 + (lane & 7) + ((lane & 16) ? 8 : 0);
    uint32_t b_base = sb + (uint32_t)(b_n * 128);
    int b_sel = (lane >> 3) & 1;
    int b_r7 = b_n & 7;

    int cr[4], cc[4];
    uint32_t cdst[4];
#pragma unroll
    for (int i = 0; i < 4; i++) {
        int e = tid + i * 256;
        cr[i] = e >> 3;
        cc[i] = e & 7;
        cdst[i] = (uint32_t)(cr[i] * 128 + ((cc[i] ^ (cr[i] & 7)) << 4));
    }

    float acc[2][8][4];
#pragma unroll
    for (int mt = 0; mt < 2; mt++)
#pragma unroll
        for (int nt = 0; nt < 8; nt++)
#pragma unroll
            for (int q = 0; q < 4; q++) acc[mt][nt][q] = 0.f;

    for (int kb = 0; kb < 4; kb++) {
        int k0 = koff + kb * 64;
#pragma unroll
        for (int i = 0; i < 4; i++) {
            int gr = row0 + cr[i];
            int ok = (gr < GM);
            size_t srcoff = (size_t)(ok ? gr : 0) * KF + k0 + cc[i] * 8;
            uint32_t sz = ok ? 16u : 0u;
            CP_ASYNC16(sb + SA_HI + cdst[i], Ahi + srcoff, sz);
            CP_ASYNC16(sb + SA_LO + cdst[i], Alo + srcoff, sz);
        }
#pragma unroll
        for (int i = 0; i < 4; i++) {
            size_t srcoff = (size_t)cr[i] * KF + k0 + cc[i] * 8;
            CP_ASYNC16(sb + SB_HI + cdst[i], g_lw_hi + srcoff, 16u);
            CP_ASYNC16(sb + SB_LO + cdst[i], g_lw_lo + srcoff, 16u);
        }
        CP_COMMIT();
        CP_WAIT0();
        __syncthreads();

#pragma unroll
        for (int ks = 0; ks < 4; ks++) {
            uint32_t aco = (uint32_t)(((2 * ks + a_sel) ^ a_r7) << 4);
            uint32_t ah[2][4], al[2][4];
#pragma unroll
            for (int mt = 0; mt < 2; mt++) {
                uint32_t ao = (uint32_t)(mt * 2048) + aco;
                LDSM_X4(ah[mt][0], ah[mt][1], ah[mt][2], ah[mt][3], a_base + SA_HI + ao);
                LDSM_X4(al[mt][0], al[mt][1], al[mt][2], al[mt][3], a_base + SA_LO + ao);
            }
            uint32_t bco = (uint32_t)(((2 * ks + b_sel) ^ b_r7) << 4);
#pragma unroll
            for (int nt2 = 0; nt2 < 4; nt2++) {
                uint32_t bo = (uint32_t)(nt2 * 2048) + bco;
                uint32_t bh0, bh1, bh2, bh3, bl0, bl1, bl2, bl3;
                LDSM_X4(bh0, bh1, bh2, bh3, b_base + SB_HI + bo);
                LDSM_X4(bl0, bl1, bl2, bl3, b_base + SB_LO + bo);
#pragma unroll
                for (int mt = 0; mt < 2; mt++) {
                    mma_bf16(acc[mt][nt2 * 2],     ah[mt], bh0, bh1);
                    mma_bf16(acc[mt][nt2 * 2],     ah[mt], bl0, bl1);
                    mma_bf16(acc[mt][nt2 * 2],     al[mt], bh0, bh1);
                    mma_bf16(acc[mt][nt2 * 2 + 1], ah[mt], bh2, bh3);
                    mma_bf16(acc[mt][nt2 * 2 + 1], ah[mt], bl2, bl3);
                    mma_bf16(acc[mt][nt2 * 2 + 1], al[mt], bh2, bh3);
                }
            }
        }
        __syncthreads();
    }

    float* Y = g_apart + (size_t)slab * BN * 128;
    int group = lane >> 2, tig = lane & 3;
#pragma unroll
    for (int mt = 0; mt < 2; mt++) {
        int r1 = row0 + mrow0 + mt * 16 + group;
        int r2 = r1 + 8;
#pragma unroll
        for (int nt = 0; nt < 8; nt++) {
            int c = ncol0 + nt * 8 + tig * 2;
            if (r1 < GM) {
                Y[(size_t)r1 * 128 + c]     = acc[mt][nt][0];
                Y[(size_t)r1 * 128 + c + 1] = acc[mt][nt][1];
            }
            if (r2 < GM) {
                Y[(size_t)r2 * 128 + c]     = acc[mt][nt][2];
                Y[(size_t)r2 * 128 + c + 1] = acc[mt][nt][3];
            }
        }
    }
}

// ---------------- SpMM + relu (+skip); MLP-batched gathers; bf16 split / fused gemm3 ----------------
__global__ void k_combine(const float* __restrict__ H, const float* __restrict__ T,
                          const float* __restrict__ S,
                          __nv_bfloat16* __restrict__ Ohi, __nv_bfloat16* __restrict__ Olo,
                          const float* __restrict__ W0, const float* __restrict__ W1) {
    int row = blockIdx.x * 8 + (threadIdx.x >> 5);
    if (row >= BN) return;
    int lane = threadIdx.x & 31;
    int cnt = g_ncnt[row];
    const int* nb = &g_nbr[row * NBR_CAP];
    size_t o = (size_t)row * 128 + lane * 4;
    float4 a = *(const float4*)&H[o];
    int k = 0;
    for (; k + 4 <= cnt; k += 4) {
        int n0 = nb[k], n1 = nb[k + 1], n2 = nb[k + 2], n3 = nb[k + 3];
        float4 v0 = *(const float4*)&T[(size_t)n0 * 128 + lane * 4];
        float4 v1 = *(const float4*)&T[(size_t)n1 * 128 + lane * 4];
        float4 v2 = *(const float4*)&T[(size_t)n2 * 128 + lane * 4];
        float4 v3 = *(const float4*)&T[(size_t)n3 * 128 + lane * 4];
        a.x += (v0.x + v1.x) + (v2.x + v3.x);
        a.y += (v0.y + v1.y) + (v2.y + v3.y);
        a.z += (v0.z + v1.z) + (v2.z + v3.z);
        a.w += (v0.w + v1.w) + (v2.w + v3.w);
    }
    for (; k < cnt; k++) {
        const float4 v = *(const float4*)&T[(size_t)nb[k] * 128 + lane * 4];
        a.x += v.x; a.y += v.y; a.z += v.z; a.w += v.w;
    }
    a.x = fmaxf(a.x, 0.f); a.y = fmaxf(a.y, 0.f);
    a.z = fmaxf(a.z, 0.f); a.w = fmaxf(a.w, 0.f);
    if (S) {
        const float4 s = *(const float4*)&S[o];
        a.x += s.x; a.y += s.y; a.z += s.z; a.w += s.w;
    }
    float vv[4] = {a.x, a.y, a.z, a.w};
    if (Ohi) {
        __nv_bfloat16 h[4], l[4];
#pragma unroll
        for (int q = 0; q < 4; q++) {
            h[q] = __float2bfloat16(vv[q]);
            l[q] = __float2bfloat16(vv[q] - __bfloat162float(h[q]));
        }
        uint2 hp, lp;
        memcpy(&hp, h, 8);
        memcpy(&lp, l, 8);
        *(uint2*)&Ohi[o] = hp;
        *(uint2*)&Olo[o] = lp;
    }
    if (W0) {
        float s6[6] = {0.f, 0.f, 0.f, 0.f, 0.f, 0.f};
#pragma unroll
        for (int q = 0; q < 4; q++) {
            int kk = lane * 4 + q;
#pragma unroll
            for (int j = 0; j < 3; j++) {
                s6[j]     += vv[q] * W0[kk * 3 + j];
                s6[3 + j] += vv[q] * W1[kk * 3 + j];
            }
        }
#pragma unroll
        for (int off = 16; off > 0; off >>= 1)
#pragma unroll
            for (int i = 0; i < 6; i++)
                s6[i] += __shfl_xor_sync(0xffffffffu, s6[i], off);
        if (lane == 0) {
#pragma unroll
            for (int j = 0; j < 3; j++) {
                g_h3[row * 3 + j] = s6[j];
                g_t3[row * 3 + j] = s6[3 + j];
            }
        }
    }
}

// ---------------- final spmm + tanh(relu) + positions ----------------
__global__ void k_final(const float* __restrict__ pos, float* __restrict__ out) {
    int idx = blockIdx.x * blockDim.x + threadIdx.x;
    if (idx >= BN * 3) return;
    int row = idx / 3, j = idx % 3;
    int cnt = g_ncnt[row];
    const int* nb = &g_nbr[row * NBR_CAP];
    float acc = g_h3[idx];
    for (int k = 0; k < cnt; k++) acc += g_t3[(size_t)nb[k] * 3 + j];
    out[idx] = pos[idx] + tanhf(fmaxf(acc, 0.f));
}

// ---------------- launch ----------------
extern "C" void kernel_launch(void* const* d_in, const int* in_sizes, int n_in,
                              void* d_out, int out_size) {
    const float* conv0 = (const float*)d_in[0];
    const float* conv1 = (const float*)d_in[1];
    const float* conv2 = (const float*)d_in[2];
    const float* conv3 = (const float*)d_in[3];
    const float* pos   = (const float*)d_in[4];
    const float* feat  = (const float*)d_in[5];
    const float* adj   = (const float*)d_in[6];
    const float* lin_w = (const float*)d_in[7];
    const float* lin_b = (const float*)d_in[8];
    const float* rw[3][6];
    for (int r = 0; r < 3; r++)
        for (int k = 0; k < 6; k++)
            rw[r][k] = (const float*)d_in[9 + r * 6 + k];
    const float* gf_w0 = (const float*)d_in[27];
    const float* gf_w1 = (const float*)d_in[28];
    float* out = (float*)d_out;

    float *skip, *t, *h2, *hfloat;
    cudaGetSymbolAddress((void**)&skip, g_skip);
    cudaGetSymbolAddress((void**)&t, g_t);
    cudaGetSymbolAddress((void**)&h2, g_h2);
    cudaGetSymbolAddress((void**)&hfloat, g_hf);
    __nv_bfloat16 *ahi, *alo, *hhi, *hlo, *ohi, *olo;
    cudaGetSymbolAddress((void**)&ahi, g_ahi);
    cudaGetSymbolAddress((void**)&alo, g_alo);
    cudaGetSymbolAddress((void**)&hhi, g_hhi);
    cudaGetSymbolAddress((void**)&hlo, g_hlo);
    cudaGetSymbolAddress((void**)&ohi, g_ohi);
    cudaGetSymbolAddress((void**)&olo, g_olo);

    cudaFuncSetAttribute(k_mmagemm, cudaFuncAttributeMaxDynamicSharedMemorySize, SM_TOTAL);
    cudaFuncSetAttribute(k_agemm, cudaFuncAttributeMaxDynamicSharedMemorySize, SM_TOTAL);

    static cudaStream_t s_side = nullptr;
    static cudaEvent_t e_fork = nullptr, e_j1 = nullptr, e_join = nullptr;
    if (!s_side) {
        cudaStreamCreateWithFlags(&s_side, cudaStreamNonBlocking);
        cudaEventCreateWithFlags(&e_fork, cudaEventDisableTiming);
        cudaEventCreateWithFlags(&e_j1, cudaEventDisableTiming);
        cudaEventCreateWithFlags(&e_join, cudaEventDisableTiming);
    }

    WPrep wp;
    const int Ks3[3] = {259, 128, 128};
    for (int rb = 0; rb < 3; rb++) {
        int cin = Ks3[rb];
        wp.W[rb * 5 + 0] = rw[rb][0]; wp.K[rb * 5 + 0] = cin;
        wp.W[rb * 5 + 1] = rw[rb][2]; wp.K[rb * 5 + 1] = cin;
        wp.W[rb * 5 + 2] = rw[rb][3]; wp.K[rb * 5 + 2] = cin;
        wp.W[rb * 5 + 3] = rw[rb][4]; wp.K[rb * 5 + 3] = 128;
        wp.W[rb * 5 + 4] = rw[rb][5]; wp.K[rb * 5 + 4] = 128;
    }

    // fork: lin_w split first (needed by k_agemm), then csr + residual wprep
    cudaEventRecord(e_fork, 0);
    cudaStreamWaitEvent(s_side, e_fork, 0);
    k_lwprep<<<(128 * KF + 255) / 256, 256, 0, s_side>>>(lin_w);
    cudaEventRecord(e_j1, s_side);
    k_csr<<<(BN * 32 + 255) / 256, 256, 0, s_side>>>(adj);
    k_wprep<<<dim3((128 * KPAD + 255) / 256, 15), 256, 0, s_side>>>(wp);
    cudaEventRecord(e_join, s_side);

    k_prep<<<(BN + 255) / 256, 256>>>(pos);   // resets g_slot, builds active list
    k_gather<<<BN, 256>>>(conv0, conv1, conv2, conv3);
    cudaStreamWaitEvent(0, e_j1, 0);          // lin_w split ready
    k_agemm<<<dim3((GM + 127) / 128, NSLAB), 256, SM_TOTAL>>>();
    k_split<<<(BN * KPAD + 255) / 256, 256>>>(lin_b, feat, pos);

    const int RB = (GM + 127) / 128;  // 78 row tiles
    const int CB = (BN + 7) / 8;      // 1233 combine blocks
    const __nv_bfloat16* Ahis[3] = {ahi, ohi, ohi};
    const __nv_bfloat16* Alos[3] = {alo, olo, olo};
    const int ldas[3] = {KPAD, 128, 128};
    const int nkbs[3] = {5, 2, 2};

    cudaStreamWaitEvent(0, e_join, 0);

    for (int rb = 0; rb < 3; rb++) {
        TcArgs a1;
        a1.wslab[0] = rb * 5 + 0; a1.bias[0] = rw[rb][1]; a1.Y[0] = skip;
        a1.wslab[1] = rb * 5 + 1; a1.bias[1] = nullptr;   a1.Y[1] = hfloat;
        a1.wslab[2] = rb * 5 + 2; a1.bias[2] = nullptr;   a1.Y[2] = t;
        k_mmagemm<<<dim3(RB, 3), 256, SM_TOTAL>>>(Ahis[rb], Alos[rb], ldas[rb], nkbs[rb], a1);
        k_combine<<<CB, 256>>>(hfloat, t, nullptr, hhi, hlo, nullptr, nullptr);

        TcArgs a2;
        a2.wslab[0] = rb * 5 + 3; a2.bias[0] = nullptr; a2.Y[0] = h2;
        a2.wslab[1] = rb * 5 + 4; a2.bias[1] = nullptr; a2.Y[1] = t;
        a2.wslab[2] = rb * 5 + 3; a2.bias[2] = nullptr; a2.Y[2] = h2;  // unused
        k_mmagemm<<<dim3(RB, 2), 256, SM_TOTAL>>>(hhi, hlo, 128, 2, a2);
        bool last = (rb == 2);
        k_combine<<<CB, 256>>>(h2, t, skip,
                               last ? nullptr : ohi, last ? nullptr : olo,
                               last ? gf_w0 : nullptr, last ? gf_w1 : nullptr);
    }

    k_final<<<(BN * 3 + 255) / 256, 256>>>(pos, out);
}